// round 1
// baseline (speedup 1.0000x reference)
#include <cuda_runtime.h>

// Problem constants (fixed shapes)
#define BB    8       // batch
#define CIN   16      // conv input channels
#define FD    1024    // feature dim (== D)
#define TD    512     // time steps
#define DD    1024    // SRU hidden dim
#define NTOK  512     // output tokens
#define LAY   4       // SRU layers
#define MROWS (TD*BB) // 4096 GEMM rows (t-major, b-minor)
#define LOGITS_ELEMS (BB*TD*NTOK) // 2097152

// Scratch (device globals — no allocation allowed)
__device__ float g_X[(size_t)MROWS * DD];      // 16 MB: layer activations, (t*B+b, d)
__device__ float g_U[(size_t)MROWS * 3 * DD];  // 48 MB: GEMM output U

// ---------------------------------------------------------------------------
// Conv: x[t,b,f] = relu( sum_c feats[b,c,f,t]*w[c] + bias ), with smem
// transpose so both the global reads (along t) and writes (along f) coalesce.
// ---------------------------------------------------------------------------
__global__ void conv_relu_t(const float* __restrict__ feats,
                            const float* __restrict__ w,
                            const float* __restrict__ bptr,
                            float* __restrict__ X) {
    __shared__ float s[32][33];
    const int tx = threadIdx.x, ty = threadIdx.y;
    const int t = blockIdx.x * 32 + tx;
    const int f = blockIdx.y * 32 + ty;
    const int b = blockIdx.z;

    float acc = bptr[0];
    const float* base = feats + ((size_t)(b * CIN) * FD + f) * TD + t;
    #pragma unroll
    for (int c = 0; c < CIN; ++c)
        acc = fmaf(base[(size_t)c * FD * TD], w[c], acc);
    s[ty][tx] = fmaxf(acc, 0.0f);
    __syncthreads();

    const int t2 = blockIdx.x * 32 + ty;
    const int f2 = blockIdx.y * 32 + tx;
    X[(size_t)(t2 * BB + b) * DD + f2] = s[tx][ty];
}

// ---------------------------------------------------------------------------
// SGEMM: C[M,N] = A[M,K] * B[K,N]. 128x128 block tile, BK=16, 256 threads,
// 8x8 per-thread tile. MODE 0: plain store (U). MODE 1: FC epilogue with
// bias and row remap (t*B+b) -> (b*T+t).
// ---------------------------------------------------------------------------
template <int MODE>
__global__ void __launch_bounds__(256, 2)
sgemm128(const float* __restrict__ A, const float* __restrict__ B,
         float* __restrict__ C, const float* __restrict__ bias,
         int N, int K) {
    __shared__ __align__(16) float As[16][132]; // padded: conflict-free STS, 16B rows
    __shared__ __align__(16) float Bs[16][128];

    const int tid = threadIdx.x;
    const int rowBase = blockIdx.y * 128;
    const int colBase = blockIdx.x * 128;

    const int arow = tid >> 2;          // 0..63
    const int acol = (tid & 3) << 2;    // 0,4,8,12
    const int brow = tid >> 5;          // 0..7
    const int bcol = (tid & 31) << 2;   // 0..124

    const int ty = tid >> 4;            // 0..15  -> rows ty*8..
    const int tx = tid & 15;            // 0..15  -> cols tx*8..

    float acc[8][8] = {};

    for (int kt = 0; kt < K; kt += 16) {
        #pragma unroll
        for (int p = 0; p < 2; ++p) {
            float4 va = *(const float4*)(A + (size_t)(rowBase + arow + p * 64) * K + kt + acol);
            As[acol + 0][arow + p * 64] = va.x;
            As[acol + 1][arow + p * 64] = va.y;
            As[acol + 2][arow + p * 64] = va.z;
            As[acol + 3][arow + p * 64] = va.w;
            *(float4*)(&Bs[brow + p * 8][bcol]) =
                *(const float4*)(B + (size_t)(kt + brow + p * 8) * N + colBase + bcol);
        }
        __syncthreads();

        #pragma unroll
        for (int kk = 0; kk < 16; ++kk) {
            float a[8], bv[8];
            *(float4*)(&a[0])  = *(const float4*)(&As[kk][ty * 8]);
            *(float4*)(&a[4])  = *(const float4*)(&As[kk][ty * 8 + 4]);
            *(float4*)(&bv[0]) = *(const float4*)(&Bs[kk][tx * 8]);
            *(float4*)(&bv[4]) = *(const float4*)(&Bs[kk][tx * 8 + 4]);
            #pragma unroll
            for (int i = 0; i < 8; ++i)
                #pragma unroll
                for (int j = 0; j < 8; ++j)
                    acc[i][j] = fmaf(a[i], bv[j], acc[i][j]);
        }
        __syncthreads();
    }

    #pragma unroll
    for (int i = 0; i < 8; ++i) {
        const int row = rowBase + ty * 8 + i;
        int orow = row;
        if (MODE == 1) orow = (row & (BB - 1)) * TD + (row >> 3); // b*T + t
        float* crow = C + (size_t)orow * N + colBase + tx * 8;
        float v[8];
        #pragma unroll
        for (int j = 0; j < 8; ++j) {
            v[j] = acc[i][j];
            if (MODE == 1) v[j] += bias[colBase + tx * 8 + j];
        }
        *(float4*)(crow)     = *(float4*)(&v[0]);
        *(float4*)(crow + 4) = *(float4*)(&v[4]);
    }
}

// ---------------------------------------------------------------------------
// SRU recurrence + readout, fused, in-place on X.
// Each thread owns one (b,d) chain; loops t=0..T-1.
//   f = sigmoid(fp + vf*c + bf); c = f*c + (1-f)*xt;
//   r = sigmoid(rp + vr*c + br); X = r*c + (1-r)*X
// ---------------------------------------------------------------------------
__device__ __forceinline__ float sigmoidf_(float z) {
    return 1.0f / (1.0f + __expf(-z));
}

__global__ void sru_rec(const float* __restrict__ U, float* __restrict__ X,
                        const float* __restrict__ v, const float* __restrict__ bb) {
    const int idx = blockIdx.x * blockDim.x + threadIdx.x; // 0..8191
    const int b = idx >> 10;       // idx / 1024
    const int d = idx & 1023;      // idx % 1024

    const float vf = v[d],      vr = v[DD + d];
    const float bf = bb[d],     br = bb[DD + d];

    float c = 0.0f;
    for (int t = 0; t < TD; ++t) {
        const size_t row = (size_t)(t * BB + b);
        const float* u = U + row * (3 * DD);
        const float xt = u[d];
        const float fp = u[DD + d];
        const float rp = u[2 * DD + d];

        const float f = sigmoidf_(fp + vf * c + bf);
        c = f * c + (1.0f - f) * xt;
        const float r = sigmoidf_(rp + vr * c + br);

        float* xp = X + row * DD + d;
        const float xo = *xp;
        *xp = r * c + (1.0f - r) * xo;
    }
}

// ---------------------------------------------------------------------------
// Output tail: s_audio_length // 2. Input dtype (int32 vs int64) sniffed on
// device: values are in [1,512] (never 0), so int64 little-endian shows zeros
// at odd int32 words. Output written as float32 (rem==8) or int64 (rem==16).
// ---------------------------------------------------------------------------
__global__ void tail_k(const int* __restrict__ lenbuf, float* outf,
                       long long* outll, int rem) {
    const int i = threadIdx.x;
    if (i >= BB) return;
    const bool in64 = (lenbuf[1] == 0 && lenbuf[3] == 0 &&
                       lenbuf[5] == 0 && lenbuf[7] == 0);
    const long long val = in64 ? (long long)lenbuf[2 * i] : (long long)lenbuf[i];
    const long long h = val >> 1; // floor div 2, val >= 1
    if (rem >= 16)      outll[i] = h;
    else if (rem >= 8)  outf[i]  = (float)h;
}

// ---------------------------------------------------------------------------
extern "C" void kernel_launch(void* const* d_in, const int* in_sizes, int n_in,
                              void* d_out, int out_size) {
    const float* feats  = (const float*)d_in[0];
    const int*   slen   = (const int*)d_in[1];
    const float* conv_w = (const float*)d_in[2];
    const float* conv_b = (const float*)d_in[3];
    const float* sru_W  = (const float*)d_in[4];
    const float* sru_v  = (const float*)d_in[5];
    const float* sru_b  = (const float*)d_in[6];
    const float* fc_w   = (const float*)d_in[7];
    const float* fc_b   = (const float*)d_in[8];

    float* Xp = nullptr;
    float* Up = nullptr;
    cudaGetSymbolAddress((void**)&Xp, g_X);
    cudaGetSymbolAddress((void**)&Up, g_U);

    // 1) conv + relu + transpose into (t*B+b, d)
    {
        dim3 grid(TD / 32, FD / 32, BB);
        dim3 block(32, 32);
        conv_relu_t<<<grid, block>>>(feats, conv_w, conv_b, Xp);
    }

    // 2) 4 SRU layers: GEMM (X @ W_l -> U) then fused recurrence/readout
    for (int l = 0; l < LAY; ++l) {
        dim3 grid(3 * DD / 128, MROWS / 128); // (24, 32)
        sgemm128<0><<<grid, 256>>>(Xp, sru_W + (size_t)l * DD * 3 * DD, Up,
                                   nullptr, 3 * DD, DD);
        sru_rec<<<(BB * DD) / 256, 256>>>(Up, Xp,
                                          sru_v + (size_t)l * 2 * DD,
                                          sru_b + (size_t)l * 2 * DD);
    }

    // 3) FC with bias + (t,b)->(b,t) row remap, straight into d_out
    {
        dim3 grid(NTOK / 128, MROWS / 128); // (4, 32)
        sgemm128<1><<<grid, 256>>>(Xp, fc_w, (float*)d_out, fc_b, NTOK, DD);
    }

    // 4) lengths tail
    {
        const int rem = out_size - LOGITS_ELEMS;
        if (rem > 0) {
            float* outf = (float*)d_out + LOGITS_ELEMS;
            long long* outll = (long long*)((char*)d_out + (size_t)LOGITS_ELEMS * 4);
            tail_k<<<1, 32>>>(slen, outf, outll, rem);
        }
    }
}

// round 2
// speedup vs baseline: 1.1096x; 1.1096x over previous
#include <cuda_runtime.h>

// Problem constants (fixed shapes)
#define BB    8       // batch
#define CIN   16      // conv input channels
#define FD    1024    // feature dim (== D)
#define TD    512     // time steps
#define DD    1024    // SRU hidden dim
#define NTOK  512     // output tokens
#define LAY   4       // SRU layers
#define MROWS (TD*BB) // 4096 GEMM rows (t-major, b-minor)
#define LOGITS_ELEMS (BB*TD*NTOK) // 2097152

// Scratch (device globals — no allocation allowed)
__device__ float g_X[(size_t)MROWS * DD];      // 16 MB: layer activations, (t*B+b, d)
__device__ float g_U[(size_t)MROWS * 3 * DD];  // 48 MB: GEMM output U

// ---------------------------------------------------------------------------
// Conv: x[t,b,f] = relu( sum_c feats[b,c,f,t]*w[c] + bias ), smem transpose
// so both global reads (along t) and writes (along f) coalesce.
// ---------------------------------------------------------------------------
__global__ void conv_relu_t(const float* __restrict__ feats,
                            const float* __restrict__ w,
                            const float* __restrict__ bptr,
                            float* __restrict__ X) {
    __shared__ float s[32][33];
    const int tx = threadIdx.x, ty = threadIdx.y;
    const int t = blockIdx.x * 32 + tx;
    const int f = blockIdx.y * 32 + ty;
    const int b = blockIdx.z;

    float acc = bptr[0];
    const float* base = feats + ((size_t)(b * CIN) * FD + f) * TD + t;
    #pragma unroll
    for (int c = 0; c < CIN; ++c)
        acc = fmaf(base[(size_t)c * FD * TD], w[c], acc);
    s[ty][tx] = fmaxf(acc, 0.0f);
    __syncthreads();

    const int t2 = blockIdx.x * 32 + ty;
    const int f2 = blockIdx.y * 32 + tx;
    X[(size_t)(t2 * BB + b) * DD + f2] = s[tx][ty];
}

// ---------------------------------------------------------------------------
// SGEMM: C[M,N] = A[M,K] * B[K,N]. 128x128 tile, BK=16, 256 threads, 8x8/thr.
// Double-buffered smem + register-staged global prefetch, 1 sync per K-tile.
// MODE 0: plain store (U). MODE 1: FC epilogue (bias + (t,b)->(b,t) remap).
// ---------------------------------------------------------------------------
template <int MODE>
__global__ void __launch_bounds__(256, 2)
sgemm128(const float* __restrict__ A, const float* __restrict__ B,
         float* __restrict__ C, const float* __restrict__ bias,
         int N, int K) {
    __shared__ __align__(16) float As[2][16][132]; // transposed A tile, padded
    __shared__ __align__(16) float Bs[2][16][128];

    const int tid = threadIdx.x;
    const int rowBase = blockIdx.y * 128;
    const int colBase = blockIdx.x * 128;

    const int arow = tid >> 2;          // 0..63
    const int acol = (tid & 3) << 2;    // 0,4,8,12
    const int brow = tid >> 5;          // 0..7
    const int bcol = (tid & 31) << 2;   // 0..124

    const int ty = tid >> 4;            // 0..15
    const int tx = tid & 15;            // 0..15

    const float* Aptr = A + (size_t)(rowBase + arow) * K + acol;
    const float* Bptr = B + (size_t)brow * N + colBase + bcol;
    const size_t Astep = (size_t)64 * K;
    const size_t Bstep = (size_t)8 * N;

    float4 av0, av1, bv0, bv1;

    // preload tile 0 -> regs -> smem buf 0
    av0 = *(const float4*)(Aptr);
    av1 = *(const float4*)(Aptr + Astep);
    bv0 = *(const float4*)(Bptr);
    bv1 = *(const float4*)(Bptr + Bstep);
    Aptr += 16;  Bptr += (size_t)16 * N;

    As[0][acol + 0][arow]      = av0.x;
    As[0][acol + 1][arow]      = av0.y;
    As[0][acol + 2][arow]      = av0.z;
    As[0][acol + 3][arow]      = av0.w;
    As[0][acol + 0][arow + 64] = av1.x;
    As[0][acol + 1][arow + 64] = av1.y;
    As[0][acol + 2][arow + 64] = av1.z;
    As[0][acol + 3][arow + 64] = av1.w;
    *(float4*)(&Bs[0][brow][bcol])     = bv0;
    *(float4*)(&Bs[0][brow + 8][bcol]) = bv1;
    __syncthreads();

    float acc[8][8] = {};
    int buf = 0;

    for (int kt = 16; kt <= K; kt += 16) {
        const bool has = (kt < K);
        if (has) {
            av0 = *(const float4*)(Aptr);
            av1 = *(const float4*)(Aptr + Astep);
            bv0 = *(const float4*)(Bptr);
            bv1 = *(const float4*)(Bptr + Bstep);
            Aptr += 16;  Bptr += (size_t)16 * N;
        }

        #pragma unroll
        for (int kk = 0; kk < 16; ++kk) {
            float a[8], bv[8];
            *(float4*)(&a[0])  = *(const float4*)(&As[buf][kk][ty * 8]);
            *(float4*)(&a[4])  = *(const float4*)(&As[buf][kk][ty * 8 + 4]);
            *(float4*)(&bv[0]) = *(const float4*)(&Bs[buf][kk][tx * 8]);
            *(float4*)(&bv[4]) = *(const float4*)(&Bs[buf][kk][tx * 8 + 4]);
            #pragma unroll
            for (int i = 0; i < 8; ++i)
                #pragma unroll
                for (int j = 0; j < 8; ++j)
                    acc[i][j] = fmaf(a[i], bv[j], acc[i][j]);
        }

        if (has) {
            const int nb = buf ^ 1;
            As[nb][acol + 0][arow]      = av0.x;
            As[nb][acol + 1][arow]      = av0.y;
            As[nb][acol + 2][arow]      = av0.z;
            As[nb][acol + 3][arow]      = av0.w;
            As[nb][acol + 0][arow + 64] = av1.x;
            As[nb][acol + 1][arow + 64] = av1.y;
            As[nb][acol + 2][arow + 64] = av1.z;
            As[nb][acol + 3][arow + 64] = av1.w;
            *(float4*)(&Bs[nb][brow][bcol])     = bv0;
            *(float4*)(&Bs[nb][brow + 8][bcol]) = bv1;
            __syncthreads();
            buf = nb;
        }
    }

    #pragma unroll
    for (int i = 0; i < 8; ++i) {
        const int row = rowBase + ty * 8 + i;
        int orow = row;
        if (MODE == 1) orow = (row & (BB - 1)) * TD + (row >> 3); // b*T + t
        float* crow = C + (size_t)orow * N + colBase + tx * 8;
        float v[8];
        #pragma unroll
        for (int j = 0; j < 8; ++j) {
            v[j] = acc[i][j];
            if (MODE == 1) v[j] += bias[colBase + tx * 8 + j];
        }
        *(float4*)(crow)     = *(float4*)(&v[0]);
        *(float4*)(crow + 4) = *(float4*)(&v[4]);
    }
}

// ---------------------------------------------------------------------------
// SRU recurrence + readout, fused, in-place on X.
// One thread per (b,d) chain; depth-4 register prefetch ring hides memory
// latency behind the ~50cyc/step sigmoid chain. 128 blocks x 64 threads.
// ---------------------------------------------------------------------------
__device__ __forceinline__ float sigmoidf_(float z) {
    return 1.0f / (1.0f + __expf(-z));
}

#define PF 4

__global__ void __launch_bounds__(64)
sru_rec(const float* __restrict__ U, float* __restrict__ X,
        const float* __restrict__ v, const float* __restrict__ bb) {
    const int d = blockIdx.x * 64 + threadIdx.x;  // 0..1023
    const int b = blockIdx.y;                     // 0..7

    const float vf = v[d],  vr = v[DD + d];
    const float bf = bb[d], br = bb[DD + d];

    const float* u0 = U + (size_t)b * 3 * DD + d;   // + t * BB*3*DD per step
    float*       x0 = X + (size_t)b * DD + d;       // + t * BB*DD   per step
    const size_t us = (size_t)BB * 3 * DD;          // 24576
    const size_t xs = (size_t)BB * DD;              // 8192

    float xt[PF], fp[PF], rp[PF], xo[PF];
    #pragma unroll
    for (int i = 0; i < PF; ++i) {
        const float* u = u0 + (size_t)i * us;
        xt[i] = u[0];
        fp[i] = u[DD];
        rp[i] = u[2 * DD];
        xo[i] = x0[(size_t)i * xs];
    }

    float c = 0.0f;
    #pragma unroll 4
    for (int t = 0; t < TD; ++t) {
        const int s = t & (PF - 1);
        const float f = sigmoidf_(fp[s] + vf * c + bf);
        c = f * c + (1.0f - f) * xt[s];
        const float r = sigmoidf_(rp[s] + vr * c + br);
        x0[(size_t)t * xs] = r * c + (1.0f - r) * xo[s];

        const int tn = t + PF;
        if (tn < TD) {
            const float* u = u0 + (size_t)tn * us;
            xt[s] = u[0];
            fp[s] = u[DD];
            rp[s] = u[2 * DD];
            xo[s] = x0[(size_t)tn * xs];
        }
    }
}

// ---------------------------------------------------------------------------
// Output tail: s_audio_length // 2. Input dtype sniffed on device (values in
// [1,512], never 0 -> int64 has zero odd words). Output float32 (rem==8) or
// int64 (rem==16).
// ---------------------------------------------------------------------------
__global__ void tail_k(const int* __restrict__ lenbuf, float* outf,
                       long long* outll, int rem) {
    const int i = threadIdx.x;
    if (i >= BB) return;
    const bool in64 = (lenbuf[1] == 0 && lenbuf[3] == 0 &&
                       lenbuf[5] == 0 && lenbuf[7] == 0);
    const long long val = in64 ? (long long)lenbuf[2 * i] : (long long)lenbuf[i];
    const long long h = val >> 1;
    if (rem >= 16)      outll[i] = h;
    else if (rem >= 8)  outf[i]  = (float)h;
}

// ---------------------------------------------------------------------------
extern "C" void kernel_launch(void* const* d_in, const int* in_sizes, int n_in,
                              void* d_out, int out_size) {
    const float* feats  = (const float*)d_in[0];
    const int*   slen   = (const int*)d_in[1];
    const float* conv_w = (const float*)d_in[2];
    const float* conv_b = (const float*)d_in[3];
    const float* sru_W  = (const float*)d_in[4];
    const float* sru_v  = (const float*)d_in[5];
    const float* sru_b  = (const float*)d_in[6];
    const float* fc_w   = (const float*)d_in[7];
    const float* fc_b   = (const float*)d_in[8];

    float* Xp = nullptr;
    float* Up = nullptr;
    cudaGetSymbolAddress((void**)&Xp, g_X);
    cudaGetSymbolAddress((void**)&Up, g_U);

    // 1) conv + relu + transpose into (t*B+b, d)
    {
        dim3 grid(TD / 32, FD / 32, BB);
        dim3 block(32, 32);
        conv_relu_t<<<grid, block>>>(feats, conv_w, conv_b, Xp);
    }

    // 2) 4 SRU layers: GEMM (X @ W_l -> U) then fused recurrence/readout
    for (int l = 0; l < LAY; ++l) {
        dim3 grid(3 * DD / 128, MROWS / 128); // (24, 32)
        sgemm128<0><<<grid, 256>>>(Xp, sru_W + (size_t)l * DD * 3 * DD, Up,
                                   nullptr, 3 * DD, DD);
        dim3 rgrid(DD / 64, BB);              // (16, 8) = 128 blocks
        sru_rec<<<rgrid, 64>>>(Up, Xp,
                               sru_v + (size_t)l * 2 * DD,
                               sru_b + (size_t)l * 2 * DD);
    }

    // 3) FC with bias + (t,b)->(b,t) row remap, straight into d_out
    {
        dim3 grid(NTOK / 128, MROWS / 128); // (4, 32)
        sgemm128<1><<<grid, 256>>>(Xp, fc_w, (float*)d_out, fc_b, NTOK, DD);
    }

    // 4) lengths tail
    {
        const int rem = out_size - LOGITS_ELEMS;
        if (rem > 0) {
            float* outf = (float*)d_out + LOGITS_ELEMS;
            long long* outll = (long long*)((char*)d_out + (size_t)LOGITS_ELEMS * 4);
            tail_k<<<1, 32>>>(slen, outf, outll, rem);
        }
    }
}

// round 4
// speedup vs baseline: 2.1685x; 1.9543x over previous
#include <cuda_runtime.h>
#include <cuda_bf16.h>
#include <cstdint>

// ---------------------------------------------------------------- shapes
#define BB    8
#define CIN   16
#define FD    1024
#define TD    512
#define DD    1024
#define NTOK  512
#define LAY   4
#define MROWS (TD*BB)                 // 4096
#define LOGITS_ELEMS (BB*TD*NTOK)     // 2097152
#define KTOT  DD                      // 1024
#define NSRU  (3*DD)                  // 3072

// ---------------------------------------------------------------- scratch
__device__ float         g_X  [(size_t)MROWS * DD];    // activations fp32
__device__ __nv_bfloat16 g_Xhi[(size_t)MROWS * DD];    // bf16 hi split of X
__device__ __nv_bfloat16 g_Xlo[(size_t)MROWS * DD];    // bf16 residual
__device__ float         g_U  [(size_t)MROWS * NSRU];  // GEMM out
__device__ __nv_bfloat16 g_Whi[(size_t)KTOT * NSRU];   // W hi  [K,N]
__device__ __nv_bfloat16 g_Wlo[(size_t)KTOT * NSRU];   // W lo

// ---------------------------------------------------------------- helpers
__device__ __forceinline__ uint32_t s2u(const void* p) {
    uint32_t a;
    asm("{ .reg .u64 t; cvta.to.shared.u64 t, %1; cvt.u32.u64 %0, t; }"
        : "=r"(a) : "l"(p));
    return a;
}
__device__ __forceinline__ void cpasync16(uint32_t dst, const void* src) {
    asm volatile("cp.async.cg.shared.global [%0], [%1], 16;"
                 :: "r"(dst), "l"(src) : "memory");
}
__device__ __forceinline__ void cp_commit() {
    asm volatile("cp.async.commit_group;" ::: "memory");
}
template <int N>
__device__ __forceinline__ void cp_wait() {
    asm volatile("cp.async.wait_group %0;" :: "n"(N) : "memory");
}
__device__ __forceinline__ void ldm_x4(uint32_t a[4], uint32_t addr) {
    asm volatile("ldmatrix.sync.aligned.m8n8.x4.shared.b16 {%0,%1,%2,%3}, [%4];"
                 : "=r"(a[0]), "=r"(a[1]), "=r"(a[2]), "=r"(a[3]) : "r"(addr));
}
__device__ __forceinline__ void ldm_x2t(uint32_t b[2], uint32_t addr) {
    asm volatile("ldmatrix.sync.aligned.m8n8.x2.trans.shared.b16 {%0,%1}, [%2];"
                 : "=r"(b[0]), "=r"(b[1]) : "r"(addr));
}
__device__ __forceinline__ void mma_bf16(float c[4], const uint32_t a[4],
                                         const uint32_t b[2]) {
    asm volatile(
        "mma.sync.aligned.m16n8k16.row.col.f32.bf16.bf16.f32 "
        "{%0,%1,%2,%3}, {%4,%5,%6,%7}, {%8,%9}, {%0,%1,%2,%3};"
        : "+f"(c[0]), "+f"(c[1]), "+f"(c[2]), "+f"(c[3])
        : "r"(a[0]), "r"(a[1]), "r"(a[2]), "r"(a[3]), "r"(b[0]), "r"(b[1]));
}

// smem layout (bytes, per stage): Ahi[128][40]b16=10240, Alo=10240,
// Bhi[32][136]b16=8704, Blo=8704 -> 37888/stage, 3 stages = 113664.
#define A_PAD   40
#define B_PAD   136
#define AOFF_LO 10240
#define BOFF_HI 20480
#define BOFF_LO 29184
#define STAGE_B 37888
#define NSTAGES 3
#define SMEM_GEMM (NSTAGES * STAGE_B)
#define NKITER (KTOT / 32)

// ---------------------------------------------------------------- GEMM
// C[M, Nglob] = A[M,K] * W[K,Nglob], 3xBF16 (hi*hi + hi*lo + lo*hi), fp32 acc.
// Block 128x128, BK=32, 256 thr, warp tile 32x64 (wm=wid%4, wn=wid/4).
// MODE 0: plain store. MODE 1: bias + (t*B+b)->(b*T+t) row remap.
__device__ __forceinline__ void load_stage(uint32_t st_base,
                                           const __nv_bfloat16* __restrict__ Ahi,
                                           const __nv_bfloat16* __restrict__ Alo,
                                           const __nv_bfloat16* __restrict__ Whi,
                                           const __nv_bfloat16* __restrict__ Wlo,
                                           int rowBase, int colBase, int kt,
                                           int Nglob, int tid) {
    #pragma unroll
    for (int i = 0; i < 2; ++i) {
        const int q  = tid + i * 256;        // 0..511
        const int ar = q >> 2, ac = q & 3;   // A: 128 rows x 4 chunks
        const uint32_t ad = st_base + ar * (A_PAD * 2) + ac * 16;
        const size_t asrc = (size_t)(rowBase + ar) * KTOT + kt + ac * 8;
        cpasync16(ad,           Ahi + asrc);
        cpasync16(ad + AOFF_LO, Alo + asrc);
        const int br = q >> 4, bc = q & 15;  // B: 32 rows x 16 chunks
        const uint32_t bd = st_base + BOFF_HI + br * (B_PAD * 2) + bc * 16;
        const size_t bsrc = (size_t)(kt + br) * Nglob + colBase + bc * 8;
        cpasync16(bd,                     Whi + bsrc);
        cpasync16(bd + (BOFF_LO - BOFF_HI), Wlo + bsrc);
    }
    cp_commit();
}

template <int MODE>
__global__ void __launch_bounds__(256)
gemm_bf16x3(const __nv_bfloat16* __restrict__ Ahi,
            const __nv_bfloat16* __restrict__ Alo,
            const __nv_bfloat16* __restrict__ Whi,
            const __nv_bfloat16* __restrict__ Wlo,
            float* __restrict__ C, const float* __restrict__ bias, int Nglob) {
    extern __shared__ __align__(16) char smem_raw[];
    const uint32_t sb = s2u(smem_raw);

    const int tid = threadIdx.x;
    const int wid = tid >> 5, lane = tid & 31;
    const int wm = wid & 3, wn = wid >> 2;          // 4 x 2 warps
    const int rowBase = blockIdx.y * 128;
    const int colBase = blockIdx.x * 128;

    float acc[2][8][4];
    #pragma unroll
    for (int i = 0; i < 2; ++i)
        #pragma unroll
        for (int j = 0; j < 8; ++j)
            #pragma unroll
            for (int k = 0; k < 4; ++k) acc[i][j][k] = 0.0f;

    // preload stages 0,1
    load_stage(sb,           Ahi, Alo, Whi, Wlo, rowBase, colBase, 0,  Nglob, tid);
    load_stage(sb + STAGE_B, Ahi, Alo, Whi, Wlo, rowBase, colBase, 32, Nglob, tid);

    const int lr = lane & 15;       // ldmatrix row select
    const int lc = lane >> 4;       // ldmatrix col-half select

    int st = 0;
    for (int k = 0; k < NKITER; ++k) {
        if (k + 1 < NKITER) cp_wait<1>(); else cp_wait<0>();
        __syncthreads();
        if (k + 2 < NKITER)
            load_stage(sb + ((k + 2) % NSTAGES) * STAGE_B, Ahi, Alo, Whi, Wlo,
                       rowBase, colBase, (k + 2) * 32, Nglob, tid);

        const uint32_t abase = sb + st * STAGE_B;
        const uint32_t bbase = abase + BOFF_HI;

        #pragma unroll
        for (int kk = 0; kk < 2; ++kk) {
            uint32_t a[2][2][4];   // [split][mt]
            #pragma unroll
            for (int sp = 0; sp < 2; ++sp)
                #pragma unroll
                for (int mt = 0; mt < 2; ++mt) {
                    const int row = wm * 32 + mt * 16 + lr;
                    const int col = kk * 16 + lc * 8;
                    ldm_x4(a[sp][mt],
                           abase + sp * AOFF_LO + row * (A_PAD * 2) + col * 2);
                }
            uint32_t b[2][8][2];   // [split][nt]
            #pragma unroll
            for (int sp = 0; sp < 2; ++sp)
                #pragma unroll
                for (int nt = 0; nt < 8; ++nt) {
                    const int row = kk * 16 + lr;
                    const int col = wn * 64 + nt * 8;
                    ldm_x2t(b[sp][nt],
                            bbase + sp * (BOFF_LO - BOFF_HI) +
                            row * (B_PAD * 2) + col * 2);
                }
            #pragma unroll
            for (int mt = 0; mt < 2; ++mt)
                #pragma unroll
                for (int nt = 0; nt < 8; ++nt) {
                    mma_bf16(acc[mt][nt], a[0][mt], b[0][nt]); // hi*hi
                    mma_bf16(acc[mt][nt], a[0][mt], b[1][nt]); // hi*lo
                    mma_bf16(acc[mt][nt], a[1][mt], b[0][nt]); // lo*hi
                }
        }
        __syncthreads();
        st = (st + 1) % NSTAGES;
    }

    // epilogue: m16n8 fragment layout
    const int rq = lane >> 2;        // row within 8
    const int cq = (lane & 3) * 2;   // col pair
    #pragma unroll
    for (int mt = 0; mt < 2; ++mt) {
        #pragma unroll
        for (int half = 0; half < 2; ++half) {
            const int m = rowBase + wm * 32 + mt * 16 + half * 8 + rq;
            const int orow = (MODE == 1) ? ((m & (BB - 1)) * TD + (m >> 3)) : m;
            float* crow = C + (size_t)orow * Nglob + colBase + wn * 64;
            #pragma unroll
            for (int nt = 0; nt < 8; ++nt) {
                float2 v;
                v.x = acc[mt][nt][half * 2 + 0];
                v.y = acc[mt][nt][half * 2 + 1];
                if (MODE == 1) {
                    v.x += bias[colBase + wn * 64 + nt * 8 + cq + 0];
                    v.y += bias[colBase + wn * 64 + nt * 8 + cq + 1];
                }
                *(float2*)(crow + nt * 8 + cq) = v;
            }
        }
    }
}

// ---------------------------------------------------------------- splits
__device__ __forceinline__ void bf16split(float x, __nv_bfloat16& hi,
                                          __nv_bfloat16& lo) {
    hi = __float2bfloat16(x);
    lo = __float2bfloat16(x - __bfloat162float(hi));
}

// W [K,N] fp32 -> hi/lo bf16 (elementwise, vectorized)
__global__ void split_w(const float* __restrict__ W,
                        __nv_bfloat16* __restrict__ hi,
                        __nv_bfloat16* __restrict__ lo, int n4) {
    const int i = blockIdx.x * blockDim.x + threadIdx.x;
    if (i >= n4) return;
    const float4 x = ((const float4*)W)[i];
    __nv_bfloat16 h[4], l[4];
    bf16split(x.x, h[0], l[0]);
    bf16split(x.y, h[1], l[1]);
    bf16split(x.z, h[2], l[2]);
    bf16split(x.w, h[3], l[3]);
    ((ulonglong1*)hi)[i] = *(ulonglong1*)h;
    ((ulonglong1*)lo)[i] = *(ulonglong1*)l;
}

// ---------------------------------------------------------------- conv
__global__ void conv_relu_t(const float* __restrict__ feats,
                            const float* __restrict__ w,
                            const float* __restrict__ bptr,
                            float* __restrict__ X,
                            __nv_bfloat16* __restrict__ Xhi,
                            __nv_bfloat16* __restrict__ Xlo) {
    __shared__ float s[32][33];
    const int tx = threadIdx.x, ty = threadIdx.y;
    const int t = blockIdx.x * 32 + tx;
    const int f = blockIdx.y * 32 + ty;
    const int b = blockIdx.z;

    float acc = bptr[0];
    const float* base = feats + ((size_t)(b * CIN) * FD + f) * TD + t;
    #pragma unroll
    for (int c = 0; c < CIN; ++c)
        acc = fmaf(base[(size_t)c * FD * TD], w[c], acc);
    s[ty][tx] = fmaxf(acc, 0.0f);
    __syncthreads();

    const int t2 = blockIdx.x * 32 + ty;
    const int f2 = blockIdx.y * 32 + tx;
    const float x = s[tx][ty];
    const size_t o = (size_t)(t2 * BB + b) * DD + f2;
    __nv_bfloat16 h, l;
    bf16split(x, h, l);
    X[o] = x;  Xhi[o] = h;  Xlo[o] = l;
}

// ---------------------------------------------------------------- SRU recurrence
__device__ __forceinline__ float sigmoidf_(float z) {
    return 1.0f / (1.0f + __expf(-z));
}
#define PF 8

__global__ void __launch_bounds__(64)
sru_rec(const float* __restrict__ U, float* __restrict__ X,
        __nv_bfloat16* __restrict__ Xhi, __nv_bfloat16* __restrict__ Xlo,
        const float* __restrict__ v, const float* __restrict__ bb) {
    const int d = blockIdx.x * 64 + threadIdx.x;
    const int b = blockIdx.y;

    const float vf = v[d],  vr = v[DD + d];
    const float bf = bb[d], br = bb[DD + d];

    const float* u0 = U + (size_t)b * 3 * DD + d;
    const size_t xoff = (size_t)b * DD + d;
    float* x0 = X + xoff;
    __nv_bfloat16* xh = Xhi + xoff;
    __nv_bfloat16* xl = Xlo + xoff;
    const size_t us = (size_t)BB * 3 * DD;
    const size_t xs = (size_t)BB * DD;

    float xt[PF], fp[PF], rp[PF], xo[PF];
    #pragma unroll
    for (int i = 0; i < PF; ++i) {
        const float* u = u0 + (size_t)i * us;
        xt[i] = u[0];
        fp[i] = u[DD];
        rp[i] = u[2 * DD];
        xo[i] = x0[(size_t)i * xs];
    }

    float c = 0.0f;
    #pragma unroll 8
    for (int t = 0; t < TD; ++t) {
        const int s = t & (PF - 1);
        const float f = sigmoidf_(fp[s] + vf * c + bf);
        c = f * c + (1.0f - f) * xt[s];
        const float r = sigmoidf_(rp[s] + vr * c + br);
        const float h = r * c + (1.0f - r) * xo[s];
        __nv_bfloat16 hh, ll;
        bf16split(h, hh, ll);
        x0[(size_t)t * xs] = h;
        xh[(size_t)t * xs] = hh;
        xl[(size_t)t * xs] = ll;

        const int tn = t + PF;
        if (tn < TD) {
            const float* u = u0 + (size_t)tn * us;
            xt[s] = u[0];
            fp[s] = u[DD];
            rp[s] = u[2 * DD];
            xo[s] = x0[(size_t)tn * xs];
        }
    }
}

// ---------------------------------------------------------------- lengths tail
__global__ void tail_k(const int* __restrict__ lenbuf, float* outf,
                       long long* outll, int rem) {
    const int i = threadIdx.x;
    if (i >= BB) return;
    const bool in64 = (lenbuf[1] == 0 && lenbuf[3] == 0 &&
                       lenbuf[5] == 0 && lenbuf[7] == 0);
    const long long val = in64 ? (long long)lenbuf[2 * i] : (long long)lenbuf[i];
    const long long h = val >> 1;
    if (rem >= 16)      outll[i] = h;
    else if (rem >= 8)  outf[i]  = (float)h;
}

// ---------------------------------------------------------------- host side
extern "C" void kernel_launch(void* const* d_in, const int* in_sizes, int n_in,
                              void* d_out, int out_size) {
    const float* feats  = (const float*)d_in[0];
    const int*   slen   = (const int*)d_in[1];
    const float* conv_w = (const float*)d_in[2];
    const float* conv_b = (const float*)d_in[3];
    const float* sru_W  = (const float*)d_in[4];
    const float* sru_v  = (const float*)d_in[5];
    const float* sru_b  = (const float*)d_in[6];
    const float* fc_w   = (const float*)d_in[7];
    const float* fc_b   = (const float*)d_in[8];

    float *Xp, *Up;
    __nv_bfloat16 *Xhi, *Xlo, *Whi, *Wlo;
    cudaGetSymbolAddress((void**)&Xp,  g_X);
    cudaGetSymbolAddress((void**)&Xhi, g_Xhi);
    cudaGetSymbolAddress((void**)&Xlo, g_Xlo);
    cudaGetSymbolAddress((void**)&Up,  g_U);
    cudaGetSymbolAddress((void**)&Whi, g_Whi);
    cudaGetSymbolAddress((void**)&Wlo, g_Wlo);

    cudaFuncSetAttribute(gemm_bf16x3<0>,
                         cudaFuncAttributeMaxDynamicSharedMemorySize, SMEM_GEMM);
    cudaFuncSetAttribute(gemm_bf16x3<1>,
                         cudaFuncAttributeMaxDynamicSharedMemorySize, SMEM_GEMM);

    // 1) conv + relu + transpose (+ bf16 split)
    {
        dim3 grid(TD / 32, FD / 32, BB);
        conv_relu_t<<<grid, dim3(32, 32)>>>(feats, conv_w, conv_b, Xp, Xhi, Xlo);
    }

    // 2) SRU layers
    for (int l = 0; l < LAY; ++l) {
        const int n4 = KTOT * NSRU / 4;
        split_w<<<(n4 + 255) / 256, 256>>>(sru_W + (size_t)l * KTOT * NSRU,
                                           Whi, Wlo, n4);
        gemm_bf16x3<0><<<dim3(NSRU / 128, MROWS / 128), 256, SMEM_GEMM>>>(
            Xhi, Xlo, Whi, Wlo, Up, nullptr, NSRU);
        sru_rec<<<dim3(DD / 64, BB), 64>>>(Up, Xp, Xhi, Xlo,
                                           sru_v + (size_t)l * 2 * DD,
                                           sru_b + (size_t)l * 2 * DD);
    }

    // 3) FC (bias + (t,b)->(b,t) remap) straight into d_out
    {
        const int n4 = KTOT * NTOK / 4;
        split_w<<<(n4 + 255) / 256, 256>>>(fc_w, Whi, Wlo, n4);
        gemm_bf16x3<1><<<dim3(NTOK / 128, MROWS / 128), 256, SMEM_GEMM>>>(
            Xhi, Xlo, Whi, Wlo, (float*)d_out, fc_b, NTOK);
    }

    // 4) lengths tail
    {
        const int rem = out_size - LOGITS_ELEMS;
        if (rem > 0) {
            float* outf = (float*)d_out + LOGITS_ELEMS;
            long long* outll = (long long*)((char*)d_out + (size_t)LOGITS_ELEMS * 4);
            tail_k<<<1, 32>>>(slen, outf, outll, rem);
        }
    }
}

// round 5
// speedup vs baseline: 2.3992x; 1.1064x over previous
#include <cuda_runtime.h>
#include <cuda_bf16.h>
#include <cstdint>

// ---------------------------------------------------------------- shapes
#define BB    8
#define CIN   16
#define FD    1024
#define TD    512
#define DD    1024
#define NTOK  512
#define LAY   4
#define MROWS (TD*BB)                 // 4096
#define LOGITS_ELEMS (BB*TD*NTOK)     // 2097152
#define KTOT  DD                      // 1024
#define NSRU  (3*DD)                  // 3072
#define WELEMS ((size_t)(LAY*NSRU + NTOK) * KTOT)  // all weights

// ---------------------------------------------------------------- scratch
__device__ float         g_X  [(size_t)MROWS * DD];    // activations fp32
__device__ __nv_bfloat16 g_Xhi[(size_t)MROWS * DD];    // bf16 hi split of X
__device__ __nv_bfloat16 g_Xlo[(size_t)MROWS * DD];    // bf16 residual
__device__ float         g_U  [(size_t)MROWS * NSRU];  // GEMM out
__device__ __nv_bfloat16 g_Whi[WELEMS];                // all W hi  [K,N] per seg
__device__ __nv_bfloat16 g_Wlo[WELEMS];                // all W lo

// ---------------------------------------------------------------- helpers
__device__ __forceinline__ uint32_t s2u(const void* p) {
    uint32_t a;
    asm("{ .reg .u64 t; cvta.to.shared.u64 t, %1; cvt.u32.u64 %0, t; }"
        : "=r"(a) : "l"(p));
    return a;
}
__device__ __forceinline__ void cpasync16(uint32_t dst, const void* src) {
    asm volatile("cp.async.cg.shared.global [%0], [%1], 16;"
                 :: "r"(dst), "l"(src) : "memory");
}
__device__ __forceinline__ void cpasync4(uint32_t dst, const void* src) {
    asm volatile("cp.async.ca.shared.global [%0], [%1], 4;"
                 :: "r"(dst), "l"(src) : "memory");
}
__device__ __forceinline__ void cp_commit() {
    asm volatile("cp.async.commit_group;" ::: "memory");
}
template <int N>
__device__ __forceinline__ void cp_wait() {
    asm volatile("cp.async.wait_group %0;" :: "n"(N) : "memory");
}
__device__ __forceinline__ void ldm_x4(uint32_t a[4], uint32_t addr) {
    asm volatile("ldmatrix.sync.aligned.m8n8.x4.shared.b16 {%0,%1,%2,%3}, [%4];"
                 : "=r"(a[0]), "=r"(a[1]), "=r"(a[2]), "=r"(a[3]) : "r"(addr));
}
__device__ __forceinline__ void ldm_x2t(uint32_t b[2], uint32_t addr) {
    asm volatile("ldmatrix.sync.aligned.m8n8.x2.trans.shared.b16 {%0,%1}, [%2];"
                 : "=r"(b[0]), "=r"(b[1]) : "r"(addr));
}
__device__ __forceinline__ void mma_bf16(float c[4], const uint32_t a[4],
                                         const uint32_t b[2]) {
    asm volatile(
        "mma.sync.aligned.m16n8k16.row.col.f32.bf16.bf16.f32 "
        "{%0,%1,%2,%3}, {%4,%5,%6,%7}, {%8,%9}, {%0,%1,%2,%3};"
        : "+f"(c[0]), "+f"(c[1]), "+f"(c[2]), "+f"(c[3])
        : "r"(a[0]), "r"(a[1]), "r"(a[2]), "r"(a[3]), "r"(b[0]), "r"(b[1]));
}
__device__ __forceinline__ float ex2f(float x) {
    float r;
    asm("ex2.approx.f32 %0, %1;" : "=f"(r) : "f"(x));
    return r;
}
__device__ __forceinline__ float rcpf(float x) {
    float r;
    asm("rcp.approx.f32 %0, %1;" : "=f"(r) : "f"(x));
    return r;
}

// smem layout (bytes, per stage): Ahi[128][40]b16=10240, Alo=10240,
// Bhi[32][136]b16=8704, Blo=8704 -> 37888/stage, 3 stages = 113664.
#define A_PAD   40
#define B_PAD   136
#define AOFF_LO 10240
#define BOFF_HI 20480
#define BOFF_LO 29184
#define STAGE_B 37888
#define NSTAGES 3
#define SMEM_GEMM (NSTAGES * STAGE_B)
#define NKITER (KTOT / 32)

// ---------------------------------------------------------------- GEMM
__device__ __forceinline__ void load_stage(uint32_t st_base,
                                           const __nv_bfloat16* __restrict__ Ahi,
                                           const __nv_bfloat16* __restrict__ Alo,
                                           const __nv_bfloat16* __restrict__ Whi,
                                           const __nv_bfloat16* __restrict__ Wlo,
                                           int rowBase, int colBase, int kt,
                                           int Nglob, int tid) {
    #pragma unroll
    for (int i = 0; i < 2; ++i) {
        const int q  = tid + i * 256;        // 0..511
        const int ar = q >> 2, ac = q & 3;   // A: 128 rows x 4 chunks
        const uint32_t ad = st_base + ar * (A_PAD * 2) + ac * 16;
        const size_t asrc = (size_t)(rowBase + ar) * KTOT + kt + ac * 8;
        cpasync16(ad,           Ahi + asrc);
        cpasync16(ad + AOFF_LO, Alo + asrc);
        const int br = q >> 4, bc = q & 15;  // B: 32 rows x 16 chunks
        const uint32_t bd = st_base + BOFF_HI + br * (B_PAD * 2) + bc * 16;
        const size_t bsrc = (size_t)(kt + br) * Nglob + colBase + bc * 8;
        cpasync16(bd,                       Whi + bsrc);
        cpasync16(bd + (BOFF_LO - BOFF_HI), Wlo + bsrc);
    }
    cp_commit();
}

template <int MODE>
__global__ void __launch_bounds__(256)
gemm_bf16x3(const __nv_bfloat16* __restrict__ Ahi,
            const __nv_bfloat16* __restrict__ Alo,
            const __nv_bfloat16* __restrict__ Whi,
            const __nv_bfloat16* __restrict__ Wlo,
            float* __restrict__ C, const float* __restrict__ bias, int Nglob) {
    extern __shared__ __align__(16) char smem_raw[];
    const uint32_t sb = s2u(smem_raw);

    const int tid = threadIdx.x;
    const int wid = tid >> 5, lane = tid & 31;
    const int wm = wid & 3, wn = wid >> 2;          // 4 x 2 warps
    const int rowBase = blockIdx.y * 128;
    const int colBase = blockIdx.x * 128;

    float acc[2][8][4];
    #pragma unroll
    for (int i = 0; i < 2; ++i)
        #pragma unroll
        for (int j = 0; j < 8; ++j)
            #pragma unroll
            for (int k = 0; k < 4; ++k) acc[i][j][k] = 0.0f;

    load_stage(sb,           Ahi, Alo, Whi, Wlo, rowBase, colBase, 0,  Nglob, tid);
    load_stage(sb + STAGE_B, Ahi, Alo, Whi, Wlo, rowBase, colBase, 32, Nglob, tid);

    const int lr = lane & 15;
    const int lc = lane >> 4;

    int st = 0;
    for (int k = 0; k < NKITER; ++k) {
        if (k + 1 < NKITER) cp_wait<1>(); else cp_wait<0>();
        __syncthreads();
        if (k + 2 < NKITER)
            load_stage(sb + ((k + 2) % NSTAGES) * STAGE_B, Ahi, Alo, Whi, Wlo,
                       rowBase, colBase, (k + 2) * 32, Nglob, tid);

        const uint32_t abase = sb + st * STAGE_B;
        const uint32_t bbase = abase + BOFF_HI;

        #pragma unroll
        for (int kk = 0; kk < 2; ++kk) {
            uint32_t a[2][2][4];
            #pragma unroll
            for (int sp = 0; sp < 2; ++sp)
                #pragma unroll
                for (int mt = 0; mt < 2; ++mt) {
                    const int row = wm * 32 + mt * 16 + lr;
                    const int col = kk * 16 + lc * 8;
                    ldm_x4(a[sp][mt],
                           abase + sp * AOFF_LO + row * (A_PAD * 2) + col * 2);
                }
            uint32_t b[2][8][2];
            #pragma unroll
            for (int sp = 0; sp < 2; ++sp)
                #pragma unroll
                for (int nt = 0; nt < 8; ++nt) {
                    const int row = kk * 16 + lr;
                    const int col = wn * 64 + nt * 8;
                    ldm_x2t(b[sp][nt],
                            bbase + sp * (BOFF_LO - BOFF_HI) +
                            row * (B_PAD * 2) + col * 2);
                }
            #pragma unroll
            for (int mt = 0; mt < 2; ++mt)
                #pragma unroll
                for (int nt = 0; nt < 8; ++nt) {
                    mma_bf16(acc[mt][nt], a[0][mt], b[0][nt]);
                    mma_bf16(acc[mt][nt], a[0][mt], b[1][nt]);
                    mma_bf16(acc[mt][nt], a[1][mt], b[0][nt]);
                }
        }
        __syncthreads();
        st = (st + 1) % NSTAGES;
    }

    const int rq = lane >> 2;
    const int cq = (lane & 3) * 2;
    #pragma unroll
    for (int mt = 0; mt < 2; ++mt) {
        #pragma unroll
        for (int half = 0; half < 2; ++half) {
            const int m = rowBase + wm * 32 + mt * 16 + half * 8 + rq;
            const int orow = (MODE == 1) ? ((m & (BB - 1)) * TD + (m >> 3)) : m;
            float* crow = C + (size_t)orow * Nglob + colBase + wn * 64;
            #pragma unroll
            for (int nt = 0; nt < 8; ++nt) {
                float2 v;
                v.x = acc[mt][nt][half * 2 + 0];
                v.y = acc[mt][nt][half * 2 + 1];
                if (MODE == 1) {
                    v.x += bias[colBase + wn * 64 + nt * 8 + cq + 0];
                    v.y += bias[colBase + wn * 64 + nt * 8 + cq + 1];
                }
                *(float2*)(crow + nt * 8 + cq) = v;
            }
        }
    }
}

// ---------------------------------------------------------------- splits
__device__ __forceinline__ void bf16split(float x, __nv_bfloat16& hi,
                                          __nv_bfloat16& lo) {
    hi = __float2bfloat16(x);
    lo = __float2bfloat16(x - __bfloat162float(hi));
}

// One kernel: split all SRU weights + FC weights into g_Whi/g_Wlo.
__global__ void split_all(const float* __restrict__ Wsru,
                          const float* __restrict__ Wfc,
                          __nv_bfloat16* __restrict__ hi,
                          __nv_bfloat16* __restrict__ lo) {
    const size_t n4sru = (size_t)LAY * NSRU * KTOT / 4;
    const size_t n4    = WELEMS / 4;
    const size_t i = (size_t)blockIdx.x * blockDim.x + threadIdx.x;
    if (i >= n4) return;
    const float4 x = (i < n4sru) ? ((const float4*)Wsru)[i]
                                 : ((const float4*)Wfc)[i - n4sru];
    __nv_bfloat16 h[4], l[4];
    bf16split(x.x, h[0], l[0]);
    bf16split(x.y, h[1], l[1]);
    bf16split(x.z, h[2], l[2]);
    bf16split(x.w, h[3], l[3]);
    ((ulonglong1*)hi)[i] = *(ulonglong1*)h;
    ((ulonglong1*)lo)[i] = *(ulonglong1*)l;
}

// ---------------------------------------------------------------- conv
__global__ void conv_relu_t(const float* __restrict__ feats,
                            const float* __restrict__ w,
                            const float* __restrict__ bptr,
                            float* __restrict__ X,
                            __nv_bfloat16* __restrict__ Xhi,
                            __nv_bfloat16* __restrict__ Xlo) {
    __shared__ float s[32][33];
    const int tx = threadIdx.x, ty = threadIdx.y;
    const int t = blockIdx.x * 32 + tx;
    const int f = blockIdx.y * 32 + ty;
    const int b = blockIdx.z;

    float acc = bptr[0];
    const float* base = feats + ((size_t)(b * CIN) * FD + f) * TD + t;
    #pragma unroll
    for (int c = 0; c < CIN; ++c)
        acc = fmaf(base[(size_t)c * FD * TD], w[c], acc);
    s[ty][tx] = fmaxf(acc, 0.0f);
    __syncthreads();

    const int t2 = blockIdx.x * 32 + ty;
    const int f2 = blockIdx.y * 32 + tx;
    const float x = s[tx][ty];
    const size_t o = (size_t)(t2 * BB + b) * DD + f2;
    __nv_bfloat16 h, l;
    bf16split(x, h, l);
    X[o] = x;  Xhi[o] = h;  Xlo[o] = l;
}

// ---------------------------------------------------------------- SRU recurrence
// cp.async smem ring (depth 16, per-thread groups, no __syncthreads).
// Critical chain per step: fma -> ex2 -> add -> rcp -> sub/fma (~48cyc).
#define RDEPTH 16
#define RPD    15   // prefetch distance

__global__ void __launch_bounds__(64)
sru_rec(const float* __restrict__ U, float* __restrict__ X,
        __nv_bfloat16* __restrict__ Xhi, __nv_bfloat16* __restrict__ Xlo,
        const float* __restrict__ v, const float* __restrict__ bb) {
    // fields: 0=xt 1=fp 2=rp 3=xo ; [field][stage][64]
    __shared__ float ring[4][RDEPTH][64];

    const int tid = threadIdx.x;
    const int d = blockIdx.x * 64 + tid;
    const int b = blockIdx.y;

    const float L2E = 1.4426950408889634f;
    const float vf2 = -v[d] * L2E;
    const float vr2 = -v[DD + d] * L2E;
    const float bf  = bb[d];
    const float br  = bb[DD + d];

    const float* u0 = U + (size_t)b * 3 * DD + d;
    const size_t xoff = (size_t)b * DD + d;
    float* x0 = X + xoff;
    __nv_bfloat16* xh = Xhi + xoff;
    __nv_bfloat16* xl = Xlo + xoff;
    const size_t us = (size_t)BB * 3 * DD;
    const size_t xs = (size_t)BB * DD;

    const uint32_t rb = s2u(&ring[0][0][0]) + tid * 4;
    #define SLOT(fld, s) (rb + ((fld) * RDEPTH + (s)) * 256)

    // prologue: prefetch steps 0..RPD-1
    #pragma unroll 1
    for (int t = 0; t < RPD; ++t) {
        const int s = t;  // t % RDEPTH
        const float* u = u0 + (size_t)t * us;
        cpasync4(SLOT(0, s), u);
        cpasync4(SLOT(1, s), u + DD);
        cpasync4(SLOT(2, s), u + 2 * DD);
        cpasync4(SLOT(3, s), x0 + (size_t)t * xs);
        cp_commit();
    }

    float c = 0.0f;
    #pragma unroll 4
    for (int t = 0; t < TD; ++t) {
        cp_wait<RPD - 1>();
        const int s = t & (RDEPTH - 1);
        float xt, fp, rp, xo;
        asm volatile("ld.shared.f32 %0, [%1];" : "=f"(xt) : "r"(SLOT(0, s)));
        asm volatile("ld.shared.f32 %0, [%1];" : "=f"(fp) : "r"(SLOT(1, s)));
        asm volatile("ld.shared.f32 %0, [%1];" : "=f"(rp) : "r"(SLOT(2, s)));
        asm volatile("ld.shared.f32 %0, [%1];" : "=f"(xo) : "r"(SLOT(3, s)));

        const int tp = t + RPD;
        if (tp < TD) {
            const int sp = tp & (RDEPTH - 1);
            const float* u = u0 + (size_t)tp * us;
            cpasync4(SLOT(0, sp), u);
            cpasync4(SLOT(1, sp), u + DD);
            cpasync4(SLOT(2, sp), u + 2 * DD);
            cpasync4(SLOT(3, sp), x0 + (size_t)tp * xs);
        }
        cp_commit();

        // f-sigmoid (critical chain)
        const float zf = fmaf(vf2, c, -(fp + bf) * L2E);
        const float f  = rcpf(1.0f + ex2f(zf));
        c = fmaf(f, c - xt, xt);
        // r-sigmoid + readout (off chain)
        const float zr = fmaf(vr2, c, -(rp + br) * L2E);
        const float r  = rcpf(1.0f + ex2f(zr));
        const float h  = fmaf(r, c - xo, xo);

        __nv_bfloat16 hh, ll;
        bf16split(h, hh, ll);
        x0[(size_t)t * xs] = h;
        xh[(size_t)t * xs] = hh;
        xl[(size_t)t * xs] = ll;
    }
    #undef SLOT
}

// ---------------------------------------------------------------- lengths tail
__global__ void tail_k(const int* __restrict__ lenbuf, float* outf,
                       long long* outll, int rem) {
    const int i = threadIdx.x;
    if (i >= BB) return;
    const bool in64 = (lenbuf[1] == 0 && lenbuf[3] == 0 &&
                       lenbuf[5] == 0 && lenbuf[7] == 0);
    const long long val = in64 ? (long long)lenbuf[2 * i] : (long long)lenbuf[i];
    const long long h = val >> 1;
    if (rem >= 16)      outll[i] = h;
    else if (rem >= 8)  outf[i]  = (float)h;
}

// ---------------------------------------------------------------- host side
extern "C" void kernel_launch(void* const* d_in, const int* in_sizes, int n_in,
                              void* d_out, int out_size) {
    const float* feats  = (const float*)d_in[0];
    const int*   slen   = (const int*)d_in[1];
    const float* conv_w = (const float*)d_in[2];
    const float* conv_b = (const float*)d_in[3];
    const float* sru_W  = (const float*)d_in[4];
    const float* sru_v  = (const float*)d_in[5];
    const float* sru_b  = (const float*)d_in[6];
    const float* fc_w   = (const float*)d_in[7];
    const float* fc_b   = (const float*)d_in[8];

    float *Xp, *Up;
    __nv_bfloat16 *Xhi, *Xlo, *Whi, *Wlo;
    cudaGetSymbolAddress((void**)&Xp,  g_X);
    cudaGetSymbolAddress((void**)&Xhi, g_Xhi);
    cudaGetSymbolAddress((void**)&Xlo, g_Xlo);
    cudaGetSymbolAddress((void**)&Up,  g_U);
    cudaGetSymbolAddress((void**)&Whi, g_Whi);
    cudaGetSymbolAddress((void**)&Wlo, g_Wlo);

    cudaFuncSetAttribute(gemm_bf16x3<0>,
                         cudaFuncAttributeMaxDynamicSharedMemorySize, SMEM_GEMM);
    cudaFuncSetAttribute(gemm_bf16x3<1>,
                         cudaFuncAttributeMaxDynamicSharedMemorySize, SMEM_GEMM);

    // 0) split all weights once
    {
        const size_t n4 = WELEMS / 4;
        split_all<<<(int)((n4 + 255) / 256), 256>>>(sru_W, fc_w, Whi, Wlo);
    }

    // 1) conv + relu + transpose (+ bf16 split)
    {
        dim3 grid(TD / 32, FD / 32, BB);
        conv_relu_t<<<grid, dim3(32, 32)>>>(feats, conv_w, conv_b, Xp, Xhi, Xlo);
    }

    // 2) SRU layers
    for (int l = 0; l < LAY; ++l) {
        const size_t woff = (size_t)l * KTOT * NSRU;
        gemm_bf16x3<0><<<dim3(NSRU / 128, MROWS / 128), 256, SMEM_GEMM>>>(
            Xhi, Xlo, Whi + woff, Wlo + woff, Up, nullptr, NSRU);
        sru_rec<<<dim3(DD / 64, BB), 64>>>(Up, Xp, Xhi, Xlo,
                                           sru_v + (size_t)l * 2 * DD,
                                           sru_b + (size_t)l * 2 * DD);
    }

    // 3) FC (bias + (t,b)->(b,t) remap) straight into d_out
    {
        const size_t woff = (size_t)LAY * KTOT * NSRU;
        gemm_bf16x3<1><<<dim3(NTOK / 128, MROWS / 128), 256, SMEM_GEMM>>>(
            Xhi, Xlo, Whi + woff, Wlo + woff, (float*)d_out, fc_b, NTOK);
    }

    // 4) lengths tail
    {
        const int rem = out_size - LOGITS_ELEMS;
        if (rem > 0) {
            float* outf = (float*)d_out + LOGITS_ELEMS;
            long long* outll = (long long*)((char*)d_out + (size_t)LOGITS_ELEMS * 4);
            tail_k<<<1, 32>>>(slen, outf, outll, rem);
        }
    }
}

// round 6
// speedup vs baseline: 2.6355x; 1.0985x over previous
#include <cuda_runtime.h>
#include <cuda_bf16.h>
#include <cstdint>

// ---------------------------------------------------------------- shapes
#define BB    8
#define CIN   16
#define FD    1024
#define TD    512
#define DD    1024
#define NTOK  512
#define LAY   4
#define MROWS (TD*BB)                 // 4096
#define LOGITS_ELEMS (BB*TD*NTOK)     // 2097152
#define KTOT  DD                      // 1024
#define NSRU  (3*DD)                  // 3072
#define WELEMS ((size_t)(LAY*NSRU + NTOK) * KTOT)

// ---------------------------------------------------------------- scratch
__device__ __nv_bfloat16 g_Xhi[(size_t)MROWS * DD];
__device__ __nv_bfloat16 g_Xlo[(size_t)MROWS * DD];
__device__ float         g_U  [(size_t)MROWS * NSRU];
__device__ __nv_bfloat16 g_Whi[WELEMS];
__device__ __nv_bfloat16 g_Wlo[WELEMS];

// ---------------------------------------------------------------- helpers
__device__ __forceinline__ uint32_t s2u(const void* p) {
    uint32_t a;
    asm("{ .reg .u64 t; cvta.to.shared.u64 t, %1; cvt.u32.u64 %0, t; }"
        : "=r"(a) : "l"(p));
    return a;
}
__device__ __forceinline__ void cpasync16(uint32_t dst, const void* src) {
    asm volatile("cp.async.cg.shared.global [%0], [%1], 16;"
                 :: "r"(dst), "l"(src) : "memory");
}
__device__ __forceinline__ void cpasync8(uint32_t dst, const void* src) {
    asm volatile("cp.async.ca.shared.global [%0], [%1], 8;"
                 :: "r"(dst), "l"(src) : "memory");
}
__device__ __forceinline__ void cpasync4(uint32_t dst, const void* src) {
    asm volatile("cp.async.ca.shared.global [%0], [%1], 4;"
                 :: "r"(dst), "l"(src) : "memory");
}
__device__ __forceinline__ void cp_commit() {
    asm volatile("cp.async.commit_group;" ::: "memory");
}
template <int N>
__device__ __forceinline__ void cp_wait() {
    asm volatile("cp.async.wait_group %0;" :: "n"(N) : "memory");
}
__device__ __forceinline__ void ldm_x4(uint32_t a[4], uint32_t addr) {
    asm volatile("ldmatrix.sync.aligned.m8n8.x4.shared.b16 {%0,%1,%2,%3}, [%4];"
                 : "=r"(a[0]), "=r"(a[1]), "=r"(a[2]), "=r"(a[3]) : "r"(addr));
}
__device__ __forceinline__ void ldm_x2t(uint32_t b[2], uint32_t addr) {
    asm volatile("ldmatrix.sync.aligned.m8n8.x2.trans.shared.b16 {%0,%1}, [%2];"
                 : "=r"(b[0]), "=r"(b[1]) : "r"(addr));
}
__device__ __forceinline__ void mma_bf16(float c[4], const uint32_t a[4],
                                         const uint32_t b[2]) {
    asm volatile(
        "mma.sync.aligned.m16n8k16.row.col.f32.bf16.bf16.f32 "
        "{%0,%1,%2,%3}, {%4,%5,%6,%7}, {%8,%9}, {%0,%1,%2,%3};"
        : "+f"(c[0]), "+f"(c[1]), "+f"(c[2]), "+f"(c[3])
        : "r"(a[0]), "r"(a[1]), "r"(a[2]), "r"(a[3]), "r"(b[0]), "r"(b[1]));
}
__device__ __forceinline__ float ex2f(float x) {
    float r;
    asm("ex2.approx.f32 %0, %1;" : "=f"(r) : "f"(x));
    return r;
}
__device__ __forceinline__ float rcpf(float x) {
    float r;
    asm("rcp.approx.f32 %0, %1;" : "=f"(r) : "f"(x));
    return r;
}

// smem layout per stage: Ahi[128][40]b16=10240, Alo=10240,
// Bhi[32][136]b16=8704, Blo=8704 -> 37888/stage, 3 stages = 113664.
#define A_PAD   40
#define B_PAD   136
#define AOFF_LO 10240
#define BOFF_HI 20480
#define BOFF_LO 29184
#define STAGE_B 37888
#define NSTAGES 3
#define SMEM_GEMM (NSTAGES * STAGE_B)
#define NKITER (KTOT / 32)

// ---------------------------------------------------------------- GEMM
__device__ __forceinline__ void load_stage(uint32_t st_base,
                                           const __nv_bfloat16* __restrict__ Ahi,
                                           const __nv_bfloat16* __restrict__ Alo,
                                           const __nv_bfloat16* __restrict__ Whi,
                                           const __nv_bfloat16* __restrict__ Wlo,
                                           int rowBase, int colBase, int kt,
                                           int Nglob, int tid) {
    #pragma unroll
    for (int i = 0; i < 2; ++i) {
        const int q  = tid + i * 256;
        const int ar = q >> 2, ac = q & 3;
        const uint32_t ad = st_base + ar * (A_PAD * 2) + ac * 16;
        const size_t asrc = (size_t)(rowBase + ar) * KTOT + kt + ac * 8;
        cpasync16(ad,           Ahi + asrc);
        cpasync16(ad + AOFF_LO, Alo + asrc);
        const int br = q >> 4, bc = q & 15;
        const uint32_t bd = st_base + BOFF_HI + br * (B_PAD * 2) + bc * 16;
        const size_t bsrc = (size_t)(kt + br) * Nglob + colBase + bc * 8;
        cpasync16(bd,                       Whi + bsrc);
        cpasync16(bd + (BOFF_LO - BOFF_HI), Wlo + bsrc);
    }
    cp_commit();
}

template <int MODE>
__global__ void __launch_bounds__(256, 2)
gemm_bf16x3(const __nv_bfloat16* __restrict__ Ahi,
            const __nv_bfloat16* __restrict__ Alo,
            const __nv_bfloat16* __restrict__ Whi,
            const __nv_bfloat16* __restrict__ Wlo,
            float* __restrict__ C, const float* __restrict__ bias, int Nglob) {
    extern __shared__ __align__(16) char smem_raw[];
    const uint32_t sb = s2u(smem_raw);

    const int tid = threadIdx.x;
    const int wid = tid >> 5, lane = tid & 31;
    const int wm = wid & 3, wn = wid >> 2;
    const int rowBase = blockIdx.y * 128;
    const int colBase = blockIdx.x * 128;

    float acc[2][8][4];
    #pragma unroll
    for (int i = 0; i < 2; ++i)
        #pragma unroll
        for (int j = 0; j < 8; ++j)
            #pragma unroll
            for (int k = 0; k < 4; ++k) acc[i][j][k] = 0.0f;

    load_stage(sb,           Ahi, Alo, Whi, Wlo, rowBase, colBase, 0,  Nglob, tid);
    load_stage(sb + STAGE_B, Ahi, Alo, Whi, Wlo, rowBase, colBase, 32, Nglob, tid);

    const int lr = lane & 15;
    const int lc = lane >> 4;

    int st = 0;
    for (int k = 0; k < NKITER; ++k) {
        if (k + 1 < NKITER) cp_wait<1>(); else cp_wait<0>();
        __syncthreads();
        if (k + 2 < NKITER)
            load_stage(sb + ((k + 2) % NSTAGES) * STAGE_B, Ahi, Alo, Whi, Wlo,
                       rowBase, colBase, (k + 2) * 32, Nglob, tid);

        const uint32_t abase = sb + st * STAGE_B;
        const uint32_t bbase = abase + BOFF_HI;

        #pragma unroll
        for (int kk = 0; kk < 2; ++kk) {
            const int arow0 = wm * 32 + lr;
            const int acol  = kk * 16 + lc * 8;
            uint32_t a0[2][4], a1[2][4], bfr[8][2];
            #pragma unroll
            for (int mt = 0; mt < 2; ++mt) {
                ldm_x4(a0[mt], abase + (arow0 + mt * 16) * (A_PAD * 2) + acol * 2);
                ldm_x4(a1[mt], abase + AOFF_LO +
                               (arow0 + mt * 16) * (A_PAD * 2) + acol * 2);
            }
            const int brow = kk * 16 + lr;
            #pragma unroll
            for (int nt = 0; nt < 8; ++nt)
                ldm_x2t(bfr[nt], bbase + brow * (B_PAD * 2) +
                                 (wn * 64 + nt * 8) * 2);
            #pragma unroll
            for (int mt = 0; mt < 2; ++mt)
                #pragma unroll
                for (int nt = 0; nt < 8; ++nt) {
                    mma_bf16(acc[mt][nt], a0[mt], bfr[nt]);  // hi*hi
                    mma_bf16(acc[mt][nt], a1[mt], bfr[nt]);  // lo*hi
                }
            #pragma unroll
            for (int nt = 0; nt < 8; ++nt)
                ldm_x2t(bfr[nt], bbase + (BOFF_LO - BOFF_HI) +
                                 brow * (B_PAD * 2) + (wn * 64 + nt * 8) * 2);
            #pragma unroll
            for (int mt = 0; mt < 2; ++mt)
                #pragma unroll
                for (int nt = 0; nt < 8; ++nt)
                    mma_bf16(acc[mt][nt], a0[mt], bfr[nt]);  // hi*lo
        }
        __syncthreads();
        st = (st + 1) % NSTAGES;
    }

    const int rq = lane >> 2;
    const int cq = (lane & 3) * 2;
    #pragma unroll
    for (int mt = 0; mt < 2; ++mt) {
        #pragma unroll
        for (int half = 0; half < 2; ++half) {
            const int m = rowBase + wm * 32 + mt * 16 + half * 8 + rq;
            const int orow = (MODE == 1) ? ((m & (BB - 1)) * TD + (m >> 3)) : m;
            float* crow = C + (size_t)orow * Nglob + colBase + wn * 64;
            #pragma unroll
            for (int nt = 0; nt < 8; ++nt) {
                float2 v;
                v.x = acc[mt][nt][half * 2 + 0];
                v.y = acc[mt][nt][half * 2 + 1];
                if (MODE == 1) {
                    v.x += bias[colBase + wn * 64 + nt * 8 + cq + 0];
                    v.y += bias[colBase + wn * 64 + nt * 8 + cq + 1];
                }
                *(float2*)(crow + nt * 8 + cq) = v;
            }
        }
    }
}

// ---------------------------------------------------------------- splits
__device__ __forceinline__ void bf16split(float x, __nv_bfloat16& hi,
                                          __nv_bfloat16& lo) {
    hi = __float2bfloat16(x);
    lo = __float2bfloat16(x - __bfloat162float(hi));
}

__global__ void split_all(const float* __restrict__ Wsru,
                          const float* __restrict__ Wfc,
                          __nv_bfloat16* __restrict__ hi,
                          __nv_bfloat16* __restrict__ lo) {
    const size_t n4sru = (size_t)LAY * NSRU * KTOT / 4;
    const size_t n4    = WELEMS / 4;
    const size_t i = (size_t)blockIdx.x * blockDim.x + threadIdx.x;
    if (i >= n4) return;
    const float4 x = (i < n4sru) ? ((const float4*)Wsru)[i]
                                 : ((const float4*)Wfc)[i - n4sru];
    __nv_bfloat16 h[4], l[4];
    bf16split(x.x, h[0], l[0]);
    bf16split(x.y, h[1], l[1]);
    bf16split(x.z, h[2], l[2]);
    bf16split(x.w, h[3], l[3]);
    ((ulonglong1*)hi)[i] = *(ulonglong1*)h;
    ((ulonglong1*)lo)[i] = *(ulonglong1*)l;
}

// ---------------------------------------------------------------- conv
__global__ void conv_relu_t(const float* __restrict__ feats,
                            const float* __restrict__ w,
                            const float* __restrict__ bptr,
                            __nv_bfloat16* __restrict__ Xhi,
                            __nv_bfloat16* __restrict__ Xlo) {
    __shared__ float s[32][33];
    const int tx = threadIdx.x, ty = threadIdx.y;
    const int t = blockIdx.x * 32 + tx;
    const int f = blockIdx.y * 32 + ty;
    const int b = blockIdx.z;

    float acc = bptr[0];
    const float* base = feats + ((size_t)(b * CIN) * FD + f) * TD + t;
    #pragma unroll
    for (int c = 0; c < CIN; ++c)
        acc = fmaf(base[(size_t)c * FD * TD], w[c], acc);
    s[ty][tx] = fmaxf(acc, 0.0f);
    __syncthreads();

    const int t2 = blockIdx.x * 32 + ty;
    const int f2 = blockIdx.y * 32 + tx;
    const float x = s[tx][ty];
    const size_t o = (size_t)(t2 * BB + b) * DD + f2;
    __nv_bfloat16 h, l;
    bf16split(x, h, l);
    Xhi[o] = h;  Xlo[o] = l;
}

// ---------------------------------------------------------------- SRU recurrence
// 2 chains per thread (d-pair), cp.async smem ring depth 16, per-thread
// groups, no block syncs. X kept only as bf16 hi/lo (xo = hi + lo).
#define RD  16
#define RPD 15

__global__ void __launch_bounds__(32)
sru_rec(const float* __restrict__ U,
        __nv_bfloat16* __restrict__ Xhi, __nv_bfloat16* __restrict__ Xlo,
        const float* __restrict__ v, const float* __restrict__ bb) {
    __shared__ float2         rU[3][RD][32];   // xt, fp, rp (d-pairs)
    __shared__ __nv_bfloat162 rH[RD][32];      // xo hi
    __shared__ __nv_bfloat162 rL[RD][32];      // xo lo

    const int tid = threadIdx.x;
    const int d0 = (blockIdx.x * 32 + tid) * 2;
    const int b = blockIdx.y;

    const float L2E = 1.4426950408889634f;
    const float vf20 = -v[d0]     * L2E, vf21 = -v[d0 + 1]     * L2E;
    const float vr20 = -v[DD + d0] * L2E, vr21 = -v[DD + d0 + 1] * L2E;
    const float bf0  = bb[d0],      bf1 = bb[d0 + 1];
    const float br0  = bb[DD + d0], br1 = bb[DD + d0 + 1];

    const float* u0 = U + (size_t)b * 3 * DD + d0;
    const size_t xoff = (size_t)b * DD + d0;
    __nv_bfloat16* xh = Xhi + xoff;
    __nv_bfloat16* xl = Xlo + xoff;
    const size_t us = (size_t)BB * 3 * DD;
    const size_t xs = (size_t)BB * DD;

    const uint32_t uB = s2u(&rU[0][0][0]) + tid * 8;
    const uint32_t hB = s2u(&rH[0][0])    + tid * 4;
    const uint32_t lB = s2u(&rL[0][0])    + tid * 4;
    #define USLOT(fld, s) (uB + ((fld) * RD + (s)) * 256)
    #define HSLOT(s)      (hB + (s) * 128)
    #define LSLOT(s)      (lB + (s) * 128)

    #pragma unroll 1
    for (int t = 0; t < RPD; ++t) {
        const float* u = u0 + (size_t)t * us;
        cpasync8(USLOT(0, t), u);
        cpasync8(USLOT(1, t), u + DD);
        cpasync8(USLOT(2, t), u + 2 * DD);
        cpasync4(HSLOT(t), xh + (size_t)t * xs);
        cpasync4(LSLOT(t), xl + (size_t)t * xs);
        cp_commit();
    }

    float c0 = 0.0f, c1 = 0.0f;
    #pragma unroll 4
    for (int t = 0; t < TD; ++t) {
        cp_wait<RPD - 1>();
        const int s = t & (RD - 1);
        float2 xt, fp, rp;
        uint32_t xohu, xolu;
        asm volatile("ld.shared.v2.f32 {%0,%1}, [%2];"
                     : "=f"(xt.x), "=f"(xt.y) : "r"(USLOT(0, s)));
        asm volatile("ld.shared.v2.f32 {%0,%1}, [%2];"
                     : "=f"(fp.x), "=f"(fp.y) : "r"(USLOT(1, s)));
        asm volatile("ld.shared.v2.f32 {%0,%1}, [%2];"
                     : "=f"(rp.x), "=f"(rp.y) : "r"(USLOT(2, s)));
        asm volatile("ld.shared.b32 %0, [%1];" : "=r"(xohu) : "r"(HSLOT(s)));
        asm volatile("ld.shared.b32 %0, [%1];" : "=r"(xolu) : "r"(LSLOT(s)));

        const int tp = t + RPD;
        if (tp < TD) {
            const int sp = tp & (RD - 1);
            const float* u = u0 + (size_t)tp * us;
            cpasync8(USLOT(0, sp), u);
            cpasync8(USLOT(1, sp), u + DD);
            cpasync8(USLOT(2, sp), u + 2 * DD);
            cpasync4(HSLOT(sp), xh + (size_t)tp * xs);
            cpasync4(LSLOT(sp), xl + (size_t)tp * xs);
        }
        cp_commit();

        // f-sigmoid chains
        const float zf0 = fmaf(vf20, c0, -(fp.x + bf0) * L2E);
        const float zf1 = fmaf(vf21, c1, -(fp.y + bf1) * L2E);
        const float f0 = rcpf(1.0f + ex2f(zf0));
        const float f1 = rcpf(1.0f + ex2f(zf1));
        c0 = fmaf(f0, c0 - xt.x, xt.x);
        c1 = fmaf(f1, c1 - xt.y, xt.y);
        // r-sigmoid + readout (off chain)
        const float zr0 = fmaf(vr20, c0, -(rp.x + br0) * L2E);
        const float zr1 = fmaf(vr21, c1, -(rp.y + br1) * L2E);
        const float r0 = rcpf(1.0f + ex2f(zr0));
        const float r1 = rcpf(1.0f + ex2f(zr1));
        const float2 xhf = __bfloat1622float2(*(__nv_bfloat162*)&xohu);
        const float2 xlf = __bfloat1622float2(*(__nv_bfloat162*)&xolu);
        const float xo0 = xhf.x + xlf.x;
        const float xo1 = xhf.y + xlf.y;
        const float h0 = fmaf(r0, c0 - xo0, xo0);
        const float h1 = fmaf(r1, c1 - xo1, xo1);

        __nv_bfloat16 hh0, hl0, hh1, hl1;
        bf16split(h0, hh0, hl0);
        bf16split(h1, hh1, hl1);
        *(__nv_bfloat162*)(xh + (size_t)t * xs) = __nv_bfloat162(hh0, hh1);
        *(__nv_bfloat162*)(xl + (size_t)t * xs) = __nv_bfloat162(hl0, hl1);
    }
    #undef USLOT
    #undef HSLOT
    #undef LSLOT
}

// ---------------------------------------------------------------- lengths tail
__global__ void tail_k(const int* __restrict__ lenbuf, float* outf,
                       long long* outll, int rem) {
    const int i = threadIdx.x;
    if (i >= BB) return;
    const bool in64 = (lenbuf[1] == 0 && lenbuf[3] == 0 &&
                       lenbuf[5] == 0 && lenbuf[7] == 0);
    const long long val = in64 ? (long long)lenbuf[2 * i] : (long long)lenbuf[i];
    const long long h = val >> 1;
    if (rem >= 16)      outll[i] = h;
    else if (rem >= 8)  outf[i]  = (float)h;
}

// ---------------------------------------------------------------- host side
extern "C" void kernel_launch(void* const* d_in, const int* in_sizes, int n_in,
                              void* d_out, int out_size) {
    const float* feats  = (const float*)d_in[0];
    const int*   slen   = (const int*)d_in[1];
    const float* conv_w = (const float*)d_in[2];
    const float* conv_b = (const float*)d_in[3];
    const float* sru_W  = (const float*)d_in[4];
    const float* sru_v  = (const float*)d_in[5];
    const float* sru_b  = (const float*)d_in[6];
    const float* fc_w   = (const float*)d_in[7];
    const float* fc_b   = (const float*)d_in[8];

    float* Up;
    __nv_bfloat16 *Xhi, *Xlo, *Whi, *Wlo;
    cudaGetSymbolAddress((void**)&Xhi, g_Xhi);
    cudaGetSymbolAddress((void**)&Xlo, g_Xlo);
    cudaGetSymbolAddress((void**)&Up,  g_U);
    cudaGetSymbolAddress((void**)&Whi, g_Whi);
    cudaGetSymbolAddress((void**)&Wlo, g_Wlo);

    cudaFuncSetAttribute(gemm_bf16x3<0>,
                         cudaFuncAttributeMaxDynamicSharedMemorySize, SMEM_GEMM);
    cudaFuncSetAttribute(gemm_bf16x3<1>,
                         cudaFuncAttributeMaxDynamicSharedMemorySize, SMEM_GEMM);

    // 0) split all weights once
    {
        const size_t n4 = WELEMS / 4;
        split_all<<<(int)((n4 + 255) / 256), 256>>>(sru_W, fc_w, Whi, Wlo);
    }

    // 1) conv + relu + transpose (+ bf16 split)
    {
        dim3 grid(TD / 32, FD / 32, BB);
        conv_relu_t<<<grid, dim3(32, 32)>>>(feats, conv_w, conv_b, Xhi, Xlo);
    }

    // 2) SRU layers
    for (int l = 0; l < LAY; ++l) {
        const size_t woff = (size_t)l * KTOT * NSRU;
        gemm_bf16x3<0><<<dim3(NSRU / 128, MROWS / 128), 256, SMEM_GEMM>>>(
            Xhi, Xlo, Whi + woff, Wlo + woff, Up, nullptr, NSRU);
        sru_rec<<<dim3(DD / 64, BB), 32>>>(Up, Xhi, Xlo,
                                           sru_v + (size_t)l * 2 * DD,
                                           sru_b + (size_t)l * 2 * DD);
    }

    // 3) FC (bias + (t,b)->(b,t) remap) straight into d_out
    {
        const size_t woff = (size_t)LAY * KTOT * NSRU;
        gemm_bf16x3<1><<<dim3(NTOK / 128, MROWS / 128), 256, SMEM_GEMM>>>(
            Xhi, Xlo, Whi + woff, Wlo + woff, (float*)d_out, fc_b, NTOK);
    }

    // 4) lengths tail
    {
        const int rem = out_size - LOGITS_ELEMS;
        if (rem > 0) {
            float* outf = (float*)d_out + LOGITS_ELEMS;
            long long* outll = (long long*)((char*)d_out + (size_t)LOGITS_ELEMS * 4);
            tail_k<<<1, 32>>>(slen, outf, outll, rem);
        }
    }
}

// round 7
// speedup vs baseline: 3.1307x; 1.1879x over previous
#include <cuda_runtime.h>
#include <cuda_fp16.h>
#include <cstdint>

// ---------------------------------------------------------------- shapes
#define BB    8
#define CIN   16
#define FD    1024
#define TD    512
#define DD    1024
#define NTOK  512
#define LAY   4
#define MROWS (TD*BB)                 // 4096
#define LOGITS_ELEMS (BB*TD*NTOK)     // 2097152
#define KTOT  DD                      // 1024
#define NSRU  (3*DD)                  // 3072
#define WELEMS ((size_t)(LAY*NSRU + NTOK) * KTOT)

// ---------------------------------------------------------------- scratch
__device__ __half g_Xhi[(size_t)MROWS * DD];   // fp16 hi plane of X
__device__ __half g_Xlo[(size_t)MROWS * DD];   // fp16 residual plane
__device__ float  g_U  [(size_t)MROWS * NSRU]; // GEMM out
__device__ __half g_Wh [WELEMS];               // all weights, single fp16

// ---------------------------------------------------------------- helpers
__device__ __forceinline__ uint32_t s2u(const void* p) {
    uint32_t a;
    asm("{ .reg .u64 t; cvta.to.shared.u64 t, %1; cvt.u32.u64 %0, t; }"
        : "=r"(a) : "l"(p));
    return a;
}
__device__ __forceinline__ void cpasync16(uint32_t dst, const void* src) {
    asm volatile("cp.async.cg.shared.global [%0], [%1], 16;"
                 :: "r"(dst), "l"(src) : "memory");
}
__device__ __forceinline__ void cpasync8(uint32_t dst, const void* src) {
    asm volatile("cp.async.ca.shared.global [%0], [%1], 8;"
                 :: "r"(dst), "l"(src) : "memory");
}
__device__ __forceinline__ void cpasync4(uint32_t dst, const void* src) {
    asm volatile("cp.async.ca.shared.global [%0], [%1], 4;"
                 :: "r"(dst), "l"(src) : "memory");
}
__device__ __forceinline__ void cp_commit() {
    asm volatile("cp.async.commit_group;" ::: "memory");
}
template <int N>
__device__ __forceinline__ void cp_wait() {
    asm volatile("cp.async.wait_group %0;" :: "n"(N) : "memory");
}
__device__ __forceinline__ void ldm_x4(uint32_t a[4], uint32_t addr) {
    asm volatile("ldmatrix.sync.aligned.m8n8.x4.shared.b16 {%0,%1,%2,%3}, [%4];"
                 : "=r"(a[0]), "=r"(a[1]), "=r"(a[2]), "=r"(a[3]) : "r"(addr));
}
__device__ __forceinline__ void ldm_x2t(uint32_t b[2], uint32_t addr) {
    asm volatile("ldmatrix.sync.aligned.m8n8.x2.trans.shared.b16 {%0,%1}, [%2];"
                 : "=r"(b[0]), "=r"(b[1]) : "r"(addr));
}
__device__ __forceinline__ void mma_f16(float c[4], const uint32_t a[4],
                                        const uint32_t b[2]) {
    asm volatile(
        "mma.sync.aligned.m16n8k16.row.col.f32.f16.f16.f32 "
        "{%0,%1,%2,%3}, {%4,%5,%6,%7}, {%8,%9}, {%0,%1,%2,%3};"
        : "+f"(c[0]), "+f"(c[1]), "+f"(c[2]), "+f"(c[3])
        : "r"(a[0]), "r"(a[1]), "r"(a[2]), "r"(a[3]), "r"(b[0]), "r"(b[1]));
}
__device__ __forceinline__ float ex2f(float x) {
    float r;
    asm("ex2.approx.f32 %0, %1;" : "=f"(r) : "f"(x));
    return r;
}
__device__ __forceinline__ float rcpf(float x) {
    float r;
    asm("rcp.approx.f32 %0, %1;" : "=f"(r) : "f"(x));
    return r;
}

// smem per stage (fp16): Ahi 128x40h = 10240B, Alo 10240B, B 32x136h = 8704B.
#define A_PADB  80     // bytes per A row (32 halves + 8 pad)
#define B_PADB  272    // bytes per B row (128 halves + 8 pad)
#define AOFF_LO 10240
#define BOFF    20480
#define STAGE_B 29184
#define NSTAGES 3
#define SMEM_GEMM (NSTAGES * STAGE_B)
#define NKITER (KTOT / 32)

// ---------------------------------------------------------------- GEMM
// C = (Ahi+Alo) * W, fp16 inputs, fp32 acc (2 MMA terms).
__device__ __forceinline__ void load_stage(uint32_t st_base,
                                           const __half* __restrict__ Ahi,
                                           const __half* __restrict__ Alo,
                                           const __half* __restrict__ Wh,
                                           int rowBase, int colBase, int kt,
                                           int Nglob, int tid) {
    #pragma unroll
    for (int i = 0; i < 2; ++i) {
        const int q  = tid + i * 256;        // 0..511
        const int ar = q >> 2, ac = q & 3;   // A: 128 rows x 4 x 16B
        const uint32_t ad = st_base + ar * A_PADB + ac * 16;
        const size_t asrc = (size_t)(rowBase + ar) * KTOT + kt + ac * 8;
        cpasync16(ad,           Ahi + asrc);
        cpasync16(ad + AOFF_LO, Alo + asrc);
        const int br = q >> 4, bc = q & 15;  // B: 32 rows x 16 x 16B
        const uint32_t bd = st_base + BOFF + br * B_PADB + bc * 16;
        cpasync16(bd, Wh + (size_t)(kt + br) * Nglob + colBase + bc * 8);
    }
    cp_commit();
}

template <int MODE>
__global__ void __launch_bounds__(256, 2)
gemm_f16x2(const __half* __restrict__ Ahi,
           const __half* __restrict__ Alo,
           const __half* __restrict__ Wh,
           float* __restrict__ C, const float* __restrict__ bias, int Nglob) {
    extern __shared__ __align__(16) char smem_raw[];
    const uint32_t sb = s2u(smem_raw);

    const int tid = threadIdx.x;
    const int wid = tid >> 5, lane = tid & 31;
    const int wm = wid & 3, wn = wid >> 2;
    const int rowBase = blockIdx.y * 128;
    const int colBase = blockIdx.x * 128;

    float acc[2][8][4];
    #pragma unroll
    for (int i = 0; i < 2; ++i)
        #pragma unroll
        for (int j = 0; j < 8; ++j)
            #pragma unroll
            for (int k = 0; k < 4; ++k) acc[i][j][k] = 0.0f;

    load_stage(sb,           Ahi, Alo, Wh, rowBase, colBase, 0,  Nglob, tid);
    load_stage(sb + STAGE_B, Ahi, Alo, Wh, rowBase, colBase, 32, Nglob, tid);

    const int lr = lane & 15;
    const int lc = lane >> 4;

    int st = 0;
    for (int k = 0; k < NKITER; ++k) {
        if (k + 1 < NKITER) cp_wait<1>(); else cp_wait<0>();
        __syncthreads();
        if (k + 2 < NKITER)
            load_stage(sb + ((k + 2) % NSTAGES) * STAGE_B, Ahi, Alo, Wh,
                       rowBase, colBase, (k + 2) * 32, Nglob, tid);

        const uint32_t abase = sb + st * STAGE_B;
        const uint32_t bbase = abase + BOFF;

        #pragma unroll
        for (int kk = 0; kk < 2; ++kk) {
            const int arow0 = wm * 32 + lr;
            const int acolB = (kk * 16 + lc * 8) * 2;
            uint32_t a0[2][4], a1[2][4], bfr[8][2];
            #pragma unroll
            for (int mt = 0; mt < 2; ++mt) {
                ldm_x4(a0[mt], abase + (arow0 + mt * 16) * A_PADB + acolB);
                ldm_x4(a1[mt], abase + AOFF_LO +
                               (arow0 + mt * 16) * A_PADB + acolB);
            }
            const int browB = (kk * 16 + lr) * B_PADB;
            #pragma unroll
            for (int nt = 0; nt < 8; ++nt)
                ldm_x2t(bfr[nt], bbase + browB + (wn * 64 + nt * 8) * 2);
            #pragma unroll
            for (int mt = 0; mt < 2; ++mt)
                #pragma unroll
                for (int nt = 0; nt < 8; ++nt) {
                    mma_f16(acc[mt][nt], a0[mt], bfr[nt]);  // hi * W
                    mma_f16(acc[mt][nt], a1[mt], bfr[nt]);  // lo * W
                }
        }
        __syncthreads();
        st = (st + 1) % NSTAGES;
    }

    const int rq = lane >> 2;
    const int cq = (lane & 3) * 2;
    #pragma unroll
    for (int mt = 0; mt < 2; ++mt) {
        #pragma unroll
        for (int half = 0; half < 2; ++half) {
            const int m = rowBase + wm * 32 + mt * 16 + half * 8 + rq;
            const int orow = (MODE == 1) ? ((m & (BB - 1)) * TD + (m >> 3)) : m;
            float* crow = C + (size_t)orow * Nglob + colBase + wn * 64;
            #pragma unroll
            for (int nt = 0; nt < 8; ++nt) {
                float2 v;
                v.x = acc[mt][nt][half * 2 + 0];
                v.y = acc[mt][nt][half * 2 + 1];
                if (MODE == 1) {
                    v.x += bias[colBase + wn * 64 + nt * 8 + cq + 0];
                    v.y += bias[colBase + wn * 64 + nt * 8 + cq + 1];
                }
                *(float2*)(crow + nt * 8 + cq) = v;
            }
        }
    }
}

// ---------------------------------------------------------------- splits
__device__ __forceinline__ void f16split(float x, __half& hi, __half& lo) {
    hi = __float2half_rn(x);
    lo = __float2half_rn(x - __half2float(hi));
}

// All weights (SRU + FC) -> single fp16 plane.
__global__ void split_w(const float* __restrict__ Wsru,
                        const float* __restrict__ Wfc,
                        __half* __restrict__ out) {
    const size_t n4sru = (size_t)LAY * NSRU * KTOT / 4;
    const size_t n4    = WELEMS / 4;
    const size_t i = (size_t)blockIdx.x * blockDim.x + threadIdx.x;
    if (i >= n4) return;
    const float4 x = (i < n4sru) ? ((const float4*)Wsru)[i]
                                 : ((const float4*)Wfc)[i - n4sru];
    __half h[4];
    h[0] = __float2half_rn(x.x);
    h[1] = __float2half_rn(x.y);
    h[2] = __float2half_rn(x.z);
    h[3] = __float2half_rn(x.w);
    ((ulonglong1*)out)[i] = *(ulonglong1*)h;
}

// ---------------------------------------------------------------- conv
__global__ void conv_relu_t(const float* __restrict__ feats,
                            const float* __restrict__ w,
                            const float* __restrict__ bptr,
                            __half* __restrict__ Xhi,
                            __half* __restrict__ Xlo) {
    __shared__ float s[32][33];
    const int tx = threadIdx.x, ty = threadIdx.y;
    const int t = blockIdx.x * 32 + tx;
    const int f = blockIdx.y * 32 + ty;
    const int b = blockIdx.z;

    float acc = bptr[0];
    const float* base = feats + ((size_t)(b * CIN) * FD + f) * TD + t;
    #pragma unroll
    for (int c = 0; c < CIN; ++c)
        acc = fmaf(base[(size_t)c * FD * TD], w[c], acc);
    s[ty][tx] = fmaxf(acc, 0.0f);
    __syncthreads();

    const int t2 = blockIdx.x * 32 + ty;
    const int f2 = blockIdx.y * 32 + tx;
    const float x = s[tx][ty];
    const size_t o = (size_t)(t2 * BB + b) * DD + f2;
    __half h, l;
    f16split(x, h, l);
    Xhi[o] = h;  Xlo[o] = l;
}

// ---------------------------------------------------------------- SRU recurrence
// 2 chains/thread, 16 blocks x 256 threads (2 warps per SMSP for issue
// interleaving), dynamic-smem cp.async ring depth 16, per-thread groups.
#define RD  16
#define RPD 15
#define SRU_SMEM (RD * 256 * 32)   // 3 x 8B (U) + 2 x 4B (xo hi/lo) per thr/slot

__global__ void __launch_bounds__(256)
sru_rec(const float* __restrict__ U,
        __half* __restrict__ Xhi, __half* __restrict__ Xlo,
        const float* __restrict__ v, const float* __restrict__ bb) {
    extern __shared__ char sm[];
    const uint32_t base = s2u(sm);

    const int tid = threadIdx.x;
    const int p = blockIdx.x * 256 + tid;      // chain-pair id, 0..4095
    const int d0 = (p & 511) * 2;
    const int b = p >> 9;

    const float L2E = 1.4426950408889634f;
    const float vf20 = -v[d0]      * L2E, vf21 = -v[d0 + 1]      * L2E;
    const float vr20 = -v[DD + d0] * L2E, vr21 = -v[DD + d0 + 1] * L2E;
    const float bf0 = -(bb[d0])      * L2E, bf1 = -(bb[d0 + 1])      * L2E;
    const float br0 = -(bb[DD + d0]) * L2E, br1 = -(bb[DD + d0 + 1]) * L2E;

    const float* u0 = U + (size_t)b * 3 * DD + d0;
    const size_t xoff = (size_t)b * DD + d0;
    __half* xh = Xhi + xoff;
    __half* xl = Xlo + xoff;
    const size_t us = (size_t)BB * 3 * DD;
    const size_t xs = (size_t)BB * DD;

    // ring regions: U fields [3][RD][256] x 8B, then H,L [RD][256] x 4B
    #define USLOT(fld, s) (base + (fld) * (RD * 2048) + (s) * 2048 + tid * 8)
    #define HSLOT(s)      (base + 3 * (RD * 2048) + (s) * 1024 + tid * 4)
    #define LSLOT(s)      (base + 3 * (RD * 2048) + (RD * 1024) + (s) * 1024 + tid * 4)

    #pragma unroll 1
    for (int t = 0; t < RPD; ++t) {
        const float* u = u0 + (size_t)t * us;
        cpasync8(USLOT(0, t), u);
        cpasync8(USLOT(1, t), u + DD);
        cpasync8(USLOT(2, t), u + 2 * DD);
        cpasync4(HSLOT(t), xh + (size_t)t * xs);
        cpasync4(LSLOT(t), xl + (size_t)t * xs);
        cp_commit();
    }

    float c0 = 0.0f, c1 = 0.0f;
    #pragma unroll 4
    for (int t = 0; t < TD; ++t) {
        cp_wait<RPD - 1>();
        const int s = t & (RD - 1);
        float2 xt, fp, rp;
        uint32_t xohu, xolu;
        asm volatile("ld.shared.v2.f32 {%0,%1}, [%2];"
                     : "=f"(xt.x), "=f"(xt.y) : "r"(USLOT(0, s)));
        asm volatile("ld.shared.v2.f32 {%0,%1}, [%2];"
                     : "=f"(fp.x), "=f"(fp.y) : "r"(USLOT(1, s)));
        asm volatile("ld.shared.v2.f32 {%0,%1}, [%2];"
                     : "=f"(rp.x), "=f"(rp.y) : "r"(USLOT(2, s)));
        asm volatile("ld.shared.b32 %0, [%1];" : "=r"(xohu) : "r"(HSLOT(s)));
        asm volatile("ld.shared.b32 %0, [%1];" : "=r"(xolu) : "r"(LSLOT(s)));

        const int tp = t + RPD;
        if (tp < TD) {
            const int sp = tp & (RD - 1);
            const float* u = u0 + (size_t)tp * us;
            cpasync8(USLOT(0, sp), u);
            cpasync8(USLOT(1, sp), u + DD);
            cpasync8(USLOT(2, sp), u + 2 * DD);
            cpasync4(HSLOT(sp), xh + (size_t)tp * xs);
            cpasync4(LSLOT(sp), xl + (size_t)tp * xs);
        }
        cp_commit();

        // f-sigmoid chains
        const float zf0 = fmaf(vf20, c0, fmaf(fp.x, -L2E, bf0));
        const float zf1 = fmaf(vf21, c1, fmaf(fp.y, -L2E, bf1));
        const float f0 = rcpf(1.0f + ex2f(zf0));
        const float f1 = rcpf(1.0f + ex2f(zf1));
        c0 = fmaf(f0, c0 - xt.x, xt.x);
        c1 = fmaf(f1, c1 - xt.y, xt.y);
        // r-sigmoid + readout (off chain)
        const float zr0 = fmaf(vr20, c0, fmaf(rp.x, -L2E, br0));
        const float zr1 = fmaf(vr21, c1, fmaf(rp.y, -L2E, br1));
        const float r0 = rcpf(1.0f + ex2f(zr0));
        const float r1 = rcpf(1.0f + ex2f(zr1));
        const float2 xhf = __half22float2(*(__half2*)&xohu);
        const float2 xlf = __half22float2(*(__half2*)&xolu);
        const float xo0 = xhf.x + xlf.x;
        const float xo1 = xhf.y + xlf.y;
        const float h0 = fmaf(r0, c0 - xo0, xo0);
        const float h1 = fmaf(r1, c1 - xo1, xo1);

        __half hh0, hl0, hh1, hl1;
        f16split(h0, hh0, hl0);
        f16split(h1, hh1, hl1);
        *(__half2*)(xh + (size_t)t * xs) = __halves2half2(hh0, hh1);
        *(__half2*)(xl + (size_t)t * xs) = __halves2half2(hl0, hl1);
    }
    #undef USLOT
    #undef HSLOT
    #undef LSLOT
}

// ---------------------------------------------------------------- lengths tail
__global__ void tail_k(const int* __restrict__ lenbuf, float* outf,
                       long long* outll, int rem) {
    const int i = threadIdx.x;
    if (i >= BB) return;
    const bool in64 = (lenbuf[1] == 0 && lenbuf[3] == 0 &&
                       lenbuf[5] == 0 && lenbuf[7] == 0);
    const long long val = in64 ? (long long)lenbuf[2 * i] : (long long)lenbuf[i];
    const long long h = val >> 1;
    if (rem >= 16)      outll[i] = h;
    else if (rem >= 8)  outf[i]  = (float)h;
}

// ---------------------------------------------------------------- host side
extern "C" void kernel_launch(void* const* d_in, const int* in_sizes, int n_in,
                              void* d_out, int out_size) {
    const float* feats  = (const float*)d_in[0];
    const int*   slen   = (const int*)d_in[1];
    const float* conv_w = (const float*)d_in[2];
    const float* conv_b = (const float*)d_in[3];
    const float* sru_W  = (const float*)d_in[4];
    const float* sru_v  = (const float*)d_in[5];
    const float* sru_b  = (const float*)d_in[6];
    const float* fc_w   = (const float*)d_in[7];
    const float* fc_b   = (const float*)d_in[8];

    float* Up;
    __half *Xhi, *Xlo, *Wh;
    cudaGetSymbolAddress((void**)&Xhi, g_Xhi);
    cudaGetSymbolAddress((void**)&Xlo, g_Xlo);
    cudaGetSymbolAddress((void**)&Up,  g_U);
    cudaGetSymbolAddress((void**)&Wh,  g_Wh);

    cudaFuncSetAttribute(gemm_f16x2<0>,
                         cudaFuncAttributeMaxDynamicSharedMemorySize, SMEM_GEMM);
    cudaFuncSetAttribute(gemm_f16x2<1>,
                         cudaFuncAttributeMaxDynamicSharedMemorySize, SMEM_GEMM);
    cudaFuncSetAttribute(sru_rec,
                         cudaFuncAttributeMaxDynamicSharedMemorySize, SRU_SMEM);

    // 0) all weights -> fp16 once
    {
        const size_t n4 = WELEMS / 4;
        split_w<<<(int)((n4 + 255) / 256), 256>>>(sru_W, fc_w, Wh);
    }

    // 1) conv + relu + transpose + fp16 hi/lo split
    {
        dim3 grid(TD / 32, FD / 32, BB);
        conv_relu_t<<<grid, dim3(32, 32)>>>(feats, conv_w, conv_b, Xhi, Xlo);
    }

    // 2) SRU layers
    for (int l = 0; l < LAY; ++l) {
        const size_t woff = (size_t)l * KTOT * NSRU;
        gemm_f16x2<0><<<dim3(NSRU / 128, MROWS / 128), 256, SMEM_GEMM>>>(
            Xhi, Xlo, Wh + woff, Up, nullptr, NSRU);
        sru_rec<<<16, 256, SRU_SMEM>>>(Up, Xhi, Xlo,
                                       sru_v + (size_t)l * 2 * DD,
                                       sru_b + (size_t)l * 2 * DD);
    }

    // 3) FC (bias + (t,b)->(b,t) remap) into d_out
    {
        const size_t woff = (size_t)LAY * KTOT * NSRU;
        gemm_f16x2<1><<<dim3(NTOK / 128, MROWS / 128), 256, SMEM_GEMM>>>(
            Xhi, Xlo, Wh + woff, (float*)d_out, fc_b, NTOK);
    }

    // 4) lengths tail
    {
        const int rem = out_size - LOGITS_ELEMS;
        if (rem > 0) {
            float* outf = (float*)d_out + LOGITS_ELEMS;
            long long* outll = (long long*)((char*)d_out + (size_t)LOGITS_ELEMS * 4);
            tail_k<<<1, 32>>>(slen, outf, outll, rem);
        }
    }
}

// round 8
// speedup vs baseline: 4.2205x; 1.3481x over previous
#include <cuda_runtime.h>
#include <cuda_fp16.h>
#include <cstdint>

// ---------------------------------------------------------------- shapes
#define BB    8
#define CIN   16
#define FD    1024
#define TD    512
#define DD    1024
#define NTOK  512
#define LAY   4
#define MROWS (TD*BB)                 // 4096
#define LOGITS_ELEMS (BB*TD*NTOK)     // 2097152
#define KTOT  DD                      // 1024
#define NSRU  (3*DD)                  // 3072
#define WELEMS ((size_t)(LAY*NSRU + NTOK) * KTOT)

// ---------------------------------------------------------------- scratch
__device__ __half g_Xhi[(size_t)MROWS * DD];   // fp16 hi plane of X (GEMM A)
__device__ __half g_Xlo[(size_t)MROWS * DD];   // fp16 residual (sru readout only)
__device__ float  g_U  [(size_t)MROWS * NSRU]; // GEMM out
__device__ __half g_Wh [WELEMS];               // all weights fp16

// ---------------------------------------------------------------- helpers
__device__ __forceinline__ uint32_t s2u(const void* p) {
    uint32_t a;
    asm("{ .reg .u64 t; cvta.to.shared.u64 t, %1; cvt.u32.u64 %0, t; }"
        : "=r"(a) : "l"(p));
    return a;
}
__device__ __forceinline__ void cpasync16(uint32_t dst, const void* src) {
    asm volatile("cp.async.cg.shared.global [%0], [%1], 16;"
                 :: "r"(dst), "l"(src) : "memory");
}
__device__ __forceinline__ void cp_commit() {
    asm volatile("cp.async.commit_group;" ::: "memory");
}
template <int N>
__device__ __forceinline__ void cp_wait() {
    asm volatile("cp.async.wait_group %0;" :: "n"(N) : "memory");
}
__device__ __forceinline__ void ldm_x4(uint32_t a[4], uint32_t addr) {
    asm volatile("ldmatrix.sync.aligned.m8n8.x4.shared.b16 {%0,%1,%2,%3}, [%4];"
                 : "=r"(a[0]), "=r"(a[1]), "=r"(a[2]), "=r"(a[3]) : "r"(addr));
}
__device__ __forceinline__ void ldm_x2t(uint32_t b[2], uint32_t addr) {
    asm volatile("ldmatrix.sync.aligned.m8n8.x2.trans.shared.b16 {%0,%1}, [%2];"
                 : "=r"(b[0]), "=r"(b[1]) : "r"(addr));
}
__device__ __forceinline__ void mma_f16(float c[4], const uint32_t a[4],
                                        const uint32_t b[2]) {
    asm volatile(
        "mma.sync.aligned.m16n8k16.row.col.f32.f16.f16.f32 "
        "{%0,%1,%2,%3}, {%4,%5,%6,%7}, {%8,%9}, {%0,%1,%2,%3};"
        : "+f"(c[0]), "+f"(c[1]), "+f"(c[2]), "+f"(c[3])
        : "r"(a[0]), "r"(a[1]), "r"(a[2]), "r"(a[3]), "r"(b[0]), "r"(b[1]));
}
__device__ __forceinline__ float ex2f(float x) {
    float r;
    asm("ex2.approx.f32 %0, %1;" : "=f"(r) : "f"(x));
    return r;
}
__device__ __forceinline__ float rcpf(float x) {
    float r;
    asm("rcp.approx.f32 %0, %1;" : "=f"(r) : "f"(x));
    return r;
}

// smem per stage (fp16): A 128x(32+8)h = 10240B, B 32x(128+8)h = 8704B.
#define A_PADB  80     // bytes per A row
#define B_PADB  272    // bytes per B row
#define BOFF    10240
#define STAGE_B 18944
#define NSTAGES 4
#define SMEM_GEMM (NSTAGES * STAGE_B)
#define NKITER (KTOT / 32)

// ---------------------------------------------------------------- GEMM
// C = A * W, single fp16 planes, fp32 acc.
__device__ __forceinline__ void load_stage(uint32_t st_base,
                                           const __half* __restrict__ Ah,
                                           const __half* __restrict__ Wh,
                                           int rowBase, int colBase, int kt,
                                           int Nglob, int tid) {
    #pragma unroll
    for (int i = 0; i < 2; ++i) {
        const int q  = tid + i * 256;        // 0..511
        const int ar = q >> 2, ac = q & 3;   // A: 128 rows x 4 x 16B
        cpasync16(st_base + ar * A_PADB + ac * 16,
                  Ah + (size_t)(rowBase + ar) * KTOT + kt + ac * 8);
        const int br = q >> 4, bc = q & 15;  // B: 32 rows x 16 x 16B
        cpasync16(st_base + BOFF + br * B_PADB + bc * 16,
                  Wh + (size_t)(kt + br) * Nglob + colBase + bc * 8);
    }
    cp_commit();
}

template <int MODE>
__global__ void __launch_bounds__(256, 2)
gemm_f16(const __half* __restrict__ Ah,
         const __half* __restrict__ Wh,
         float* __restrict__ C, const float* __restrict__ bias, int Nglob) {
    extern __shared__ __align__(16) char smem_raw[];
    const uint32_t sb = s2u(smem_raw);

    const int tid = threadIdx.x;
    const int wid = tid >> 5, lane = tid & 31;
    const int wm = wid & 3, wn = wid >> 2;
    const int rowBase = blockIdx.y * 128;
    const int colBase = blockIdx.x * 128;

    float acc[2][8][4];
    #pragma unroll
    for (int i = 0; i < 2; ++i)
        #pragma unroll
        for (int j = 0; j < 8; ++j)
            #pragma unroll
            for (int k = 0; k < 4; ++k) acc[i][j][k] = 0.0f;

    load_stage(sb,               Ah, Wh, rowBase, colBase, 0,  Nglob, tid);
    load_stage(sb + STAGE_B,     Ah, Wh, rowBase, colBase, 32, Nglob, tid);
    load_stage(sb + 2 * STAGE_B, Ah, Wh, rowBase, colBase, 64, Nglob, tid);

    const int lr = lane & 15;
    const int lc = lane >> 4;

    for (int k = 0; k < NKITER; ++k) {
        if (k + 3 <= NKITER) cp_wait<2>(); else if (k + 2 <= NKITER) cp_wait<1>(); else cp_wait<0>();
        __syncthreads();
        if (k + 3 < NKITER)
            load_stage(sb + ((k + 3) & 3) * STAGE_B, Ah, Wh,
                       rowBase, colBase, (k + 3) * 32, Nglob, tid);

        const uint32_t abase = sb + (k & 3) * STAGE_B;
        const uint32_t bbase = abase + BOFF;

        #pragma unroll
        for (int kk = 0; kk < 2; ++kk) {
            const int arow0 = wm * 32 + lr;
            const int acolB = (kk * 16 + lc * 8) * 2;
            uint32_t a0[2][4], bfr[8][2];
            #pragma unroll
            for (int mt = 0; mt < 2; ++mt)
                ldm_x4(a0[mt], abase + (arow0 + mt * 16) * A_PADB + acolB);
            const int browB = (kk * 16 + lr) * B_PADB;
            #pragma unroll
            for (int nt = 0; nt < 8; ++nt)
                ldm_x2t(bfr[nt], bbase + browB + (wn * 64 + nt * 8) * 2);
            #pragma unroll
            for (int mt = 0; mt < 2; ++mt)
                #pragma unroll
                for (int nt = 0; nt < 8; ++nt)
                    mma_f16(acc[mt][nt], a0[mt], bfr[nt]);
        }
        __syncthreads();
    }

    const int rq = lane >> 2;
    const int cq = (lane & 3) * 2;
    #pragma unroll
    for (int mt = 0; mt < 2; ++mt) {
        #pragma unroll
        for (int half = 0; half < 2; ++half) {
            const int m = rowBase + wm * 32 + mt * 16 + half * 8 + rq;
            const int orow = (MODE == 1) ? ((m & (BB - 1)) * TD + (m >> 3)) : m;
            float* crow = C + (size_t)orow * Nglob + colBase + wn * 64;
            #pragma unroll
            for (int nt = 0; nt < 8; ++nt) {
                float2 v;
                v.x = acc[mt][nt][half * 2 + 0];
                v.y = acc[mt][nt][half * 2 + 1];
                if (MODE == 1) {
                    v.x += bias[colBase + wn * 64 + nt * 8 + cq + 0];
                    v.y += bias[colBase + wn * 64 + nt * 8 + cq + 1];
                }
                *(float2*)(crow + nt * 8 + cq) = v;
            }
        }
    }
}

// ---------------------------------------------------------------- splits
__device__ __forceinline__ void f16split(float x, __half& hi, __half& lo) {
    hi = __float2half_rn(x);
    lo = __float2half_rn(x - __half2float(hi));
}

__global__ void split_w(const float* __restrict__ Wsru,
                        const float* __restrict__ Wfc,
                        __half* __restrict__ out) {
    const size_t n4sru = (size_t)LAY * NSRU * KTOT / 4;
    const size_t n4    = WELEMS / 4;
    const size_t i = (size_t)blockIdx.x * blockDim.x + threadIdx.x;
    if (i >= n4) return;
    const float4 x = (i < n4sru) ? ((const float4*)Wsru)[i]
                                 : ((const float4*)Wfc)[i - n4sru];
    __half h[4];
    h[0] = __float2half_rn(x.x);
    h[1] = __float2half_rn(x.y);
    h[2] = __float2half_rn(x.z);
    h[3] = __float2half_rn(x.w);
    ((ulonglong1*)out)[i] = *(ulonglong1*)h;
}

// ---------------------------------------------------------------- conv
__global__ void conv_relu_t(const float* __restrict__ feats,
                            const float* __restrict__ w,
                            const float* __restrict__ bptr,
                            __half* __restrict__ Xhi,
                            __half* __restrict__ Xlo) {
    __shared__ float s[32][33];
    const int tx = threadIdx.x, ty = threadIdx.y;
    const int t = blockIdx.x * 32 + tx;
    const int f = blockIdx.y * 32 + ty;
    const int b = blockIdx.z;

    float acc = bptr[0];
    const float* base = feats + ((size_t)(b * CIN) * FD + f) * TD + t;
    #pragma unroll
    for (int c = 0; c < CIN; ++c)
        acc = fmaf(base[(size_t)c * FD * TD], w[c], acc);
    s[ty][tx] = fmaxf(acc, 0.0f);
    __syncthreads();

    const int t2 = blockIdx.x * 32 + ty;
    const int f2 = blockIdx.y * 32 + tx;
    const float x = s[tx][ty];
    const size_t o = (size_t)(t2 * BB + b) * DD + f2;
    __half h, l;
    f16split(x, h, l);
    Xhi[o] = h;  Xlo[o] = l;
}

// ---------------------------------------------------------------- SRU recurrence
// 1 chain/thread, 128 blocks x 64 threads (256 SMSPs), LDG register ring
// RD=8 / prefetch distance 7, no smem, no syncs.
#define RD 8

__global__ void __launch_bounds__(64)
sru_rec(const float* __restrict__ U,
        __half* __restrict__ Xhi, __half* __restrict__ Xlo,
        const float* __restrict__ v, const float* __restrict__ bb) {
    const int p = blockIdx.x * 64 + threadIdx.x;   // 0..8191
    const int b = p >> 10;
    const int d = p & 1023;

    const float L2E = 1.4426950408889634f;
    const float vf2 = -v[d]      * L2E;
    const float vr2 = -v[DD + d] * L2E;
    const float bfz = -bb[d]      * L2E;
    const float brz = -bb[DD + d] * L2E;

    const float* u0 = U + (size_t)b * 3 * DD + d;
    const size_t xoff = (size_t)b * DD + d;
    __half* xh = Xhi + xoff;
    __half* xl = Xlo + xoff;
    const size_t us = (size_t)BB * 3 * DD;
    const size_t xs = (size_t)BB * DD;

    float  xt[RD], fz[RD], rz[RD];
    __half oh[RD], ol[RD];

    // prologue: prefetch steps 0..6 into slots 0..6
    #pragma unroll
    for (int i = 0; i < RD - 1; ++i) {
        const float* u = u0 + (size_t)i * us;
        xt[i] = __ldg(u);
        fz[i] = __ldg(u + DD);
        rz[i] = __ldg(u + 2 * DD);
        oh[i] = xh[(size_t)i * xs];
        ol[i] = xl[(size_t)i * xs];
    }

    float c = 0.0f;
    for (int t0 = 0; t0 < TD; t0 += RD) {
        #pragma unroll
        for (int i = 0; i < RD; ++i) {
            const int t = t0 + i;
            const float xtv = xt[i];
            const float fpv = fz[i];
            const float rpv = rz[i];
            const float xov = __half2float(oh[i]) + __half2float(ol[i]);

            // prefetch t+7 into slot (i+7)%8
            const int tp = t + RD - 1;
            if (tp < TD) {
                const int j = (i + RD - 1) & (RD - 1);
                const float* u = u0 + (size_t)tp * us;
                xt[j] = __ldg(u);
                fz[j] = __ldg(u + DD);
                rz[j] = __ldg(u + 2 * DD);
                oh[j] = xh[(size_t)tp * xs];
                ol[j] = xl[(size_t)tp * xs];
            }

            // f-sigmoid (critical chain)
            const float zf = fmaf(vf2, c, fmaf(fpv, -L2E, bfz));
            const float f  = rcpf(1.0f + ex2f(zf));
            c = fmaf(f, c - xtv, xtv);
            // r-sigmoid + readout (off chain)
            const float zr = fmaf(vr2, c, fmaf(rpv, -L2E, brz));
            const float r  = rcpf(1.0f + ex2f(zr));
            const float h  = fmaf(r, c - xov, xov);

            __half hh, hl;
            f16split(h, hh, hl);
            xh[(size_t)t * xs] = hh;
            xl[(size_t)t * xs] = hl;
        }
    }
}

// ---------------------------------------------------------------- lengths tail
__global__ void tail_k(const int* __restrict__ lenbuf, float* outf,
                       long long* outll, int rem) {
    const int i = threadIdx.x;
    if (i >= BB) return;
    const bool in64 = (lenbuf[1] == 0 && lenbuf[3] == 0 &&
                       lenbuf[5] == 0 && lenbuf[7] == 0);
    const long long val = in64 ? (long long)lenbuf[2 * i] : (long long)lenbuf[i];
    const long long h = val >> 1;
    if (rem >= 16)      outll[i] = h;
    else if (rem >= 8)  outf[i]  = (float)h;
}

// ---------------------------------------------------------------- host side
extern "C" void kernel_launch(void* const* d_in, const int* in_sizes, int n_in,
                              void* d_out, int out_size) {
    const float* feats  = (const float*)d_in[0];
    const int*   slen   = (const int*)d_in[1];
    const float* conv_w = (const float*)d_in[2];
    const float* conv_b = (const float*)d_in[3];
    const float* sru_W  = (const float*)d_in[4];
    const float* sru_v  = (const float*)d_in[5];
    const float* sru_b  = (const float*)d_in[6];
    const float* fc_w   = (const float*)d_in[7];
    const float* fc_b   = (const float*)d_in[8];

    float* Up;
    __half *Xhi, *Xlo, *Wh;
    cudaGetSymbolAddress((void**)&Xhi, g_Xhi);
    cudaGetSymbolAddress((void**)&Xlo, g_Xlo);
    cudaGetSymbolAddress((void**)&Up,  g_U);
    cudaGetSymbolAddress((void**)&Wh,  g_Wh);

    cudaFuncSetAttribute(gemm_f16<0>,
                         cudaFuncAttributeMaxDynamicSharedMemorySize, SMEM_GEMM);
    cudaFuncSetAttribute(gemm_f16<1>,
                         cudaFuncAttributeMaxDynamicSharedMemorySize, SMEM_GEMM);

    // 0) all weights -> fp16 once
    {
        const size_t n4 = WELEMS / 4;
        split_w<<<(int)((n4 + 255) / 256), 256>>>(sru_W, fc_w, Wh);
    }

    // 1) conv + relu + transpose + fp16 hi/lo split
    {
        dim3 grid(TD / 32, FD / 32, BB);
        conv_relu_t<<<grid, dim3(32, 32)>>>(feats, conv_w, conv_b, Xhi, Xlo);
    }

    // 2) SRU layers
    for (int l = 0; l < LAY; ++l) {
        const size_t woff = (size_t)l * KTOT * NSRU;
        gemm_f16<0><<<dim3(NSRU / 128, MROWS / 128), 256, SMEM_GEMM>>>(
            Xhi, Wh + woff, Up, nullptr, NSRU);
        sru_rec<<<128, 64>>>(Up, Xhi, Xlo,
                             sru_v + (size_t)l * 2 * DD,
                             sru_b + (size_t)l * 2 * DD);
    }

    // 3) FC (bias + (t,b)->(b,t) remap) into d_out
    {
        const size_t woff = (size_t)LAY * KTOT * NSRU;
        gemm_f16<1><<<dim3(NTOK / 128, MROWS / 128), 256, SMEM_GEMM>>>(
            Xhi, Wh + woff, (float*)d_out, fc_b, NTOK);
    }

    // 4) lengths tail
    {
        const int rem = out_size - LOGITS_ELEMS;
        if (rem > 0) {
            float* outf = (float*)d_out + LOGITS_ELEMS;
            long long* outll = (long long*)((char*)d_out + (size_t)LOGITS_ELEMS * 4);
            tail_k<<<1, 32>>>(slen, outf, outll, rem);
        }
    }
}